// round 6
// baseline (speedup 1.0000x reference)
#include <cuda_runtime.h>
#include <cuda_bf16.h>
#include <math.h>
#include <stdint.h>

#define B   8
#define LQ  1024
#define LK  1024
#define DD  512
#define H   8

// ---------------------------------------------------------------------------
// Device scratch (static globals — allocation-guard safe)
// ---------------------------------------------------------------------------
#define XN (8ull*1024*512)
__device__ __nv_bfloat16 g_xh[3*XN];               // inputs hi
__device__ __nv_bfloat16 g_xl[3*XN];               // inputs lo
__device__ __nv_bfloat16 g_wth[3ull*8*64*512];     // W^T hi [which][h][e][d]
__device__ __nv_bfloat16 g_wtl[3ull*8*64*512];     // W^T lo
__device__ __nv_bfloat16 g_oh[3ull*64*1024*64];    // proj out hi [which][bh][l][e]
__device__ __nv_bfloat16 g_ol[3ull*64*1024*64];    // proj out lo
__device__ __nv_bfloat16 g_vth[64ull*64*1024];     // V^T hi [bh][e][l]
__device__ __nv_bfloat16 g_vtl[64ull*64*1024];     // V^T lo
__device__ float g_conc[(size_t)B*LQ*512];

// ---------------------------------------------------------------------------
// mma.sync m16n8k16 bf16 (row.col), f32 accum + ldmatrix
// ---------------------------------------------------------------------------
#define MMA16816(c, a0, a1, a2, a3, b0, b1)                                   \
    asm volatile(                                                             \
        "mma.sync.aligned.m16n8k16.row.col.f32.bf16.bf16.f32 "                \
        "{%0,%1,%2,%3}, {%4,%5,%6,%7}, {%8,%9}, {%0,%1,%2,%3};"               \
        : "+f"((c)[0]), "+f"((c)[1]), "+f"((c)[2]), "+f"((c)[3])              \
        : "r"(a0), "r"(a1), "r"(a2), "r"(a3), "r"(b0), "r"(b1))

#define LDSM4(r0, r1, r2, r3, addr)                                           \
    asm volatile("ldmatrix.sync.aligned.m8n8.x4.shared.b16 {%0,%1,%2,%3}, [%4];" \
        : "=r"(r0), "=r"(r1), "=r"(r2), "=r"(r3) : "r"(addr))

__device__ __forceinline__ uint32_t smem_u32(const void* p) {
    uint32_t a;
    asm("{ .reg .u64 t; cvta.to.shared.u64 t, %1; cvt.u32.u64 %0, t; }"
        : "=r"(a) : "l"(p));
    return a;
}
__device__ __forceinline__ uint32_t packbf(float lo, float hi) {
    uint32_t d;
    asm("cvt.rn.bf16x2.f32 %0, %1, %2;" : "=r"(d) : "f"(hi), "f"(lo));
    return d;
}
__device__ __forceinline__ float bfres(float x) {
    return x - __bfloat162float(__float2bfloat16_rn(x));
}

// ---------------------------------------------------------------------------
// Convert inputs fp32 -> bf16 hi/lo
// ---------------------------------------------------------------------------
__global__ __launch_bounds__(256) void convert_x_kernel(
    const float* __restrict__ q, const float* __restrict__ k,
    const float* __restrict__ v)
{
    const int which = blockIdx.y;
    const float* src = (which == 0) ? q : (which == 1) ? k : v;
    size_t i4 = (size_t)blockIdx.x * 256 + threadIdx.x;
    float4 x = ((const float4*)src)[i4];
    size_t base = (size_t)which * XN + i4 * 4;

    __nv_bfloat16 h0 = __float2bfloat16(x.x);
    __nv_bfloat16 h1 = __float2bfloat16(x.y);
    __nv_bfloat16 h2 = __float2bfloat16(x.z);
    __nv_bfloat16 h3 = __float2bfloat16(x.w);
    ((__nv_bfloat162*)(g_xh + base))[0] = __halves2bfloat162(h0, h1);
    ((__nv_bfloat162*)(g_xh + base))[1] = __halves2bfloat162(h2, h3);
    ((__nv_bfloat162*)(g_xl + base))[0] = __halves2bfloat162(
        __float2bfloat16(x.x - __bfloat162float(h0)),
        __float2bfloat16(x.y - __bfloat162float(h1)));
    ((__nv_bfloat162*)(g_xl + base))[1] = __halves2bfloat162(
        __float2bfloat16(x.z - __bfloat162float(h2)),
        __float2bfloat16(x.w - __bfloat162float(h3)));
}

// ---------------------------------------------------------------------------
// Convert + transpose weights: W[h][d][e] fp32 -> g_wt{h,l}[which][h][e][d]
// ---------------------------------------------------------------------------
__global__ __launch_bounds__(256) void convert_w_kernel(
    const float* __restrict__ Wq, const float* __restrict__ Wk,
    const float* __restrict__ Wv)
{
    const int which = blockIdx.x;
    const int h     = blockIdx.y;
    const float* W = ((which == 0) ? Wq : (which == 1) ? Wk : Wv) + (size_t)h * DD * 64;
    size_t obase = ((size_t)(which * 8 + h)) * 64 * 512;
    for (int it = 0; it < 128; ++it) {
        int idx = it * 256 + threadIdx.x;
        int e = idx & 63, d = idx >> 6;
        float x = W[(size_t)d * 64 + e];
        __nv_bfloat16 hi = __float2bfloat16(x);
        g_wth[obase + (size_t)e * 512 + d] = hi;
        g_wtl[obase + (size_t)e * 512 + d] =
            __float2bfloat16(x - __bfloat162float(hi));
    }
}

// ---------------------------------------------------------------------------
// Projection via mma.sync + ldmatrix. grid (LQ/128, H, 3*B), 256 threads.
// ---------------------------------------------------------------------------
#define PLD 72
#define PROJ_SMEM ((128 * PLD * 2 + 64 * PLD * 2) * 2)  // 55296 bytes

__global__ __launch_bounds__(256) void proj_mma_kernel()
{
    extern __shared__ __nv_bfloat16 psm[];
    __nv_bfloat16* sAh = psm;
    __nv_bfloat16* sAl = psm + 128 * PLD;
    __nv_bfloat16* sBh = psm + 256 * PLD;
    __nv_bfloat16* sBl = psm + 256 * PLD + 64 * PLD;

    const int tid  = threadIdx.x;
    const int warp = tid >> 5;
    const int lane = tid & 31;
    const int r    = lane >> 2;
    const int cg   = (lane & 3) * 2;
    const int mw   = warp * 16;

    const int l0 = blockIdx.x * 128;
    const int h  = blockIdx.y;
    const int z  = blockIdx.z;
    const int which = z >> 3, b = z & 7;

    const __nv_bfloat16* xh = g_xh + (size_t)which * XN + ((size_t)b * 1024 + l0) * 512;
    const __nv_bfloat16* xl = g_xl + (size_t)which * XN + ((size_t)b * 1024 + l0) * 512;
    const __nv_bfloat16* wh = g_wth + ((size_t)(which * 8 + h)) * 64 * 512;
    const __nv_bfloat16* wl = g_wtl + ((size_t)(which * 8 + h)) * 64 * 512;

    const uint32_t sb32 = smem_u32(psm);
    // A ldmatrix byte offsets: rows mw..mw+15 (lanes 0-15), k-halves (lanes 16-31)
    const uint32_t aoff = ((mw + (lane & 15)) * PLD + ((lane >> 4) << 3)) * 2;
    // B ldmatrix: rows (lane&7 | (lane>>4)<<3) within 16-row pair, k-half (lane>>3)&1
    const uint32_t boff = (((lane & 7) | ((lane >> 4) << 3)) * PLD +
                           (((lane >> 3) & 1) << 3)) * 2;
    const uint32_t sAh32 = sb32, sAl32 = sb32 + 128 * PLD * 2;
    const uint32_t sBh32 = sb32 + 256 * PLD * 2, sBl32 = sb32 + 320 * PLD * 2;

    float c[8][4];
#pragma unroll
    for (int n = 0; n < 8; ++n)
#pragma unroll
        for (int j = 0; j < 4; ++j) c[n][j] = 0.f;

    for (int dt = 0; dt < 8; ++dt) {
        __syncthreads();
#pragma unroll
        for (int rr = 0; rr < 4; ++rr) {
            int u = tid + rr * 256;
            int row = u >> 3, cc = u & 7;
            size_t so = (size_t)row * 512 + dt * 64 + cc * 8;
            int de = row * PLD + cc * 8;
            *(uint4*)(sAh + de) = *(const uint4*)(xh + so);
            *(uint4*)(sAl + de) = *(const uint4*)(xl + so);
        }
#pragma unroll
        for (int rr = 0; rr < 2; ++rr) {
            int u = tid + rr * 256;
            int e = u >> 3, cc = u & 7;
            size_t so = (size_t)e * 512 + dt * 64 + cc * 8;
            int de = e * PLD + cc * 8;
            *(uint4*)(sBh + de) = *(const uint4*)(wh + so);
            *(uint4*)(sBl + de) = *(const uint4*)(wl + so);
        }
        __syncthreads();

#pragma unroll
        for (int ks = 0; ks < 4; ++ks) {
            uint32_t ah0, ah1, ah2, ah3, al0, al1, al2, al3;
            LDSM4(ah0, ah1, ah2, ah3, sAh32 + aoff + ks * 32);
            LDSM4(al0, al1, al2, al3, sAl32 + aoff + ks * 32);
#pragma unroll
            for (int p = 0; p < 4; ++p) {
                uint32_t bh0, bh1, bh2, bh3, bl0, bl1, bl2, bl3;
                LDSM4(bh0, bh1, bh2, bh3,
                      sBh32 + boff + p * (16 * PLD * 2) + ks * 32);
                LDSM4(bl0, bl1, bl2, bl3,
                      sBl32 + boff + p * (16 * PLD * 2) + ks * 32);
                MMA16816(c[2*p],   ah0, ah1, ah2, ah3, bh0, bh1);
                MMA16816(c[2*p],   ah0, ah1, ah2, ah3, bl0, bl1);
                MMA16816(c[2*p],   al0, al1, al2, al3, bh0, bh1);
                MMA16816(c[2*p+1], ah0, ah1, ah2, ah3, bh2, bh3);
                MMA16816(c[2*p+1], ah0, ah1, ah2, ah3, bl2, bl3);
                MMA16816(c[2*p+1], al0, al1, al2, al3, bh2, bh3);
            }
        }
    }

    size_t rowbase = ((size_t)(which * 64 + b * 8 + h) * 1024 + l0 + mw + r) * 64;
#pragma unroll
    for (int n = 0; n < 8; ++n) {
        *(uint32_t*)(g_oh + rowbase + n * 8 + cg) = packbf(c[n][0], c[n][1]);
        *(uint32_t*)(g_ol + rowbase + n * 8 + cg) =
            packbf(bfres(c[n][0]), bfres(c[n][1]));
        *(uint32_t*)(g_oh + rowbase + 8 * 64 + n * 8 + cg) = packbf(c[n][2], c[n][3]);
        *(uint32_t*)(g_ol + rowbase + 8 * 64 + n * 8 + cg) =
            packbf(bfres(c[n][2]), bfres(c[n][3]));
    }
}

// ---------------------------------------------------------------------------
// Transpose V hi/lo: g_oh/g_ol[2][bh][l][e] -> g_vth/g_vtl[bh][e][l]
// ---------------------------------------------------------------------------
__global__ __launch_bounds__(256) void vt_kernel()
{
    __shared__ __nv_bfloat16 t[32][33];
    const int bh = blockIdx.z;
    const int l0 = blockIdx.x * 32;
    const int e0 = blockIdx.y * 32;
    const int x = threadIdx.x, y = threadIdx.y;

    const __nv_bfloat16* srch = g_oh + ((size_t)(2 * 64 + bh) * 1024) * 64;
    const __nv_bfloat16* srcl = g_ol + ((size_t)(2 * 64 + bh) * 1024) * 64;
    __nv_bfloat16* dsth = g_vth + (size_t)bh * 64 * 1024;
    __nv_bfloat16* dstl = g_vtl + (size_t)bh * 64 * 1024;

#pragma unroll
    for (int rr = 0; rr < 4; ++rr)
        t[y + 8 * rr][x] = srch[(size_t)(l0 + y + 8 * rr) * 64 + e0 + x];
    __syncthreads();
#pragma unroll
    for (int rr = 0; rr < 4; ++rr)
        dsth[(size_t)(e0 + y + 8 * rr) * 1024 + l0 + x] = t[x][y + 8 * rr];
    __syncthreads();
#pragma unroll
    for (int rr = 0; rr < 4; ++rr)
        t[y + 8 * rr][x] = srcl[(size_t)(l0 + y + 8 * rr) * 64 + e0 + x];
    __syncthreads();
#pragma unroll
    for (int rr = 0; rr < 4; ++rr)
        dstl[(size_t)(e0 + y + 8 * rr) * 1024 + l0 + x] = t[x][y + 8 * rr];
}

// ---------------------------------------------------------------------------
// Flash attention via mma.sync + ldmatrix. 128 q/CTA, 64-key tiles.
// ---------------------------------------------------------------------------
#define OQH 0
#define OQL 9216
#define OKH 18432
#define OKL 23040
#define OVH 27648
#define OVL 32256
#define OMSK_BYTES 73728
#define ATTN_SMEM 73984

__global__ __launch_bounds__(256, 2) void attn_mma_kernel(const float* __restrict__ mask)
{
    extern __shared__ __nv_bfloat16 sb[];
    __nv_bfloat16* sQh = sb + OQH;   // [128][72]
    __nv_bfloat16* sQl = sb + OQL;
    __nv_bfloat16* sKh = sb + OKH;   // [64][72]
    __nv_bfloat16* sKl = sb + OKL;
    __nv_bfloat16* sVh = sb + OVH;   // [64 e][72 keys] (V^T)
    __nv_bfloat16* sVl = sb + OVL;
    float* smask = (float*)((char*)sb + OMSK_BYTES);

    const int tid  = threadIdx.x;
    const int warp = tid >> 5;
    const int lane = tid & 31;
    const int r    = lane >> 2;
    const int cg   = (lane & 3) * 2;
    const int mw   = warp * 16;

    const int q0 = blockIdx.x * 128;
    const int bh = blockIdx.y;
    const int b  = bh >> 3;
    const int hh = bh & 7;

    const __nv_bfloat16* Qh = g_oh + ((size_t)(0 * 64 + bh) * 1024 + q0) * 64;
    const __nv_bfloat16* Ql = g_ol + ((size_t)(0 * 64 + bh) * 1024 + q0) * 64;
    const __nv_bfloat16* Kh = g_oh + ((size_t)(1 * 64 + bh) * 1024) * 64;
    const __nv_bfloat16* Kl = g_ol + ((size_t)(1 * 64 + bh) * 1024) * 64;
    const __nv_bfloat16* Vth = g_vth + (size_t)bh * 64 * 1024;
    const __nv_bfloat16* Vtl = g_vtl + (size_t)bh * 64 * 1024;

    const uint32_t sb32 = smem_u32(sb);
    const uint32_t aoff = ((mw + (lane & 15)) * 72 + ((lane >> 4) << 3)) * 2;
    const uint32_t boff = (((lane & 7) | ((lane >> 4) << 3)) * 72 +
                           (((lane >> 3) & 1) << 3)) * 2;
    const uint32_t sQh32 = sb32 + OQH * 2, sQl32 = sb32 + OQL * 2;
    const uint32_t sKh32 = sb32 + OKH * 2, sKl32 = sb32 + OKL * 2;
    const uint32_t sVh32 = sb32 + OVH * 2, sVl32 = sb32 + OVL * 2;

    // stage Q once
#pragma unroll
    for (int rr = 0; rr < 4; ++rr) {
        int u = tid + rr * 256;
        int row = u >> 3, c8 = (u & 7) * 8;
        *(uint4*)(sQh + row * 72 + c8) = *(const uint4*)(Qh + (size_t)row * 64 + c8);
        *(uint4*)(sQl + row * 72 + c8) = *(const uint4*)(Ql + (size_t)row * 64 + c8);
    }

    float m[2], l[2], o[8][4];
    m[0] = m[1] = -1e30f;
    l[0] = l[1] = 0.f;
#pragma unroll
    for (int n = 0; n < 8; ++n)
#pragma unroll
        for (int j = 0; j < 4; ++j) o[n][j] = 0.f;

    for (int kt = 0; kt < 16; ++kt) {
        __syncthreads();
#pragma unroll
        for (int rr = 0; rr < 2; ++rr) {
            int u = tid + rr * 256;
            int row = u >> 3, c8 = (u & 7) * 8;
            *(uint4*)(sKh + row * 72 + c8) =
                *(const uint4*)(Kh + (size_t)(kt * 64 + row) * 64 + c8);
            *(uint4*)(sKl + row * 72 + c8) =
                *(const uint4*)(Kl + (size_t)(kt * 64 + row) * 64 + c8);
            *(uint4*)(sVh + row * 72 + c8) =
                *(const uint4*)(Vth + (size_t)row * 1024 + kt * 64 + c8);
            *(uint4*)(sVl + row * 72 + c8) =
                *(const uint4*)(Vtl + (size_t)row * 1024 + kt * 64 + c8);
        }
        if (tid < 64) smask[tid] = mask[(size_t)b * LK + kt * 64 + tid];
        __syncthreads();

        // ---- S = Q K^T (split bf16, 3 MMAs) ----
        float s[8][4];
#pragma unroll
        for (int n = 0; n < 8; ++n)
#pragma unroll
            for (int j = 0; j < 4; ++j) s[n][j] = 0.f;

#pragma unroll
        for (int ks = 0; ks < 4; ++ks) {
            uint32_t qh0, qh1, qh2, qh3, ql0, ql1, ql2, ql3;
            LDSM4(qh0, qh1, qh2, qh3, sQh32 + aoff + ks * 32);
            LDSM4(ql0, ql1, ql2, ql3, sQl32 + aoff + ks * 32);
#pragma unroll
            for (int p = 0; p < 4; ++p) {
                uint32_t kh0, kh1, kh2, kh3, kl0, kl1, kl2, kl3;
                LDSM4(kh0, kh1, kh2, kh3,
                      sKh32 + boff + p * (16 * 72 * 2) + ks * 32);
                LDSM4(kl0, kl1, kl2, kl3,
                      sKl32 + boff + p * (16 * 72 * 2) + ks * 32);
                MMA16816(s[2*p],   qh0, qh1, qh2, qh3, kh0, kh1);
                MMA16816(s[2*p],   qh0, qh1, qh2, qh3, kl0, kl1);
                MMA16816(s[2*p],   ql0, ql1, ql2, ql3, kh0, kh1);
                MMA16816(s[2*p+1], qh0, qh1, qh2, qh3, kh2, kh3);
                MMA16816(s[2*p+1], qh0, qh1, qh2, qh3, kl2, kl3);
                MMA16816(s[2*p+1], ql0, ql1, ql2, ql3, kh2, kh3);
            }
        }

        // ---- mask ----
#pragma unroll
        for (int ng = 0; ng < 8; ++ng) {
            float mk0 = smask[ng * 8 + cg];
            float mk1 = smask[ng * 8 + cg + 1];
            if (mk0 == 0.f) { s[ng][0] = -1e30f; s[ng][2] = -1e30f; }
            if (mk1 == 0.f) { s[ng][1] = -1e30f; s[ng][3] = -1e30f; }
        }

        // ---- online softmax on fragments ----
        float rm0 = -1e30f, rm1 = -1e30f;
#pragma unroll
        for (int ng = 0; ng < 8; ++ng) {
            rm0 = fmaxf(rm0, fmaxf(s[ng][0], s[ng][1]));
            rm1 = fmaxf(rm1, fmaxf(s[ng][2], s[ng][3]));
        }
        rm0 = fmaxf(rm0, __shfl_xor_sync(0xffffffffu, rm0, 1));
        rm0 = fmaxf(rm0, __shfl_xor_sync(0xffffffffu, rm0, 2));
        rm1 = fmaxf(rm1, __shfl_xor_sync(0xffffffffu, rm1, 1));
        rm1 = fmaxf(rm1, __shfl_xor_sync(0xffffffffu, rm1, 2));

        float mn0 = fmaxf(m[0], rm0), mn1 = fmaxf(m[1], rm1);
        float sc0 = __expf(m[0] - mn0), sc1 = __expf(m[1] - mn1);
        float rs0 = 0.f, rs1 = 0.f;
#pragma unroll
        for (int ng = 0; ng < 8; ++ng) {
            s[ng][0] = __expf(s[ng][0] - mn0);
            s[ng][1] = __expf(s[ng][1] - mn0);
            s[ng][2] = __expf(s[ng][2] - mn1);
            s[ng][3] = __expf(s[ng][3] - mn1);
            rs0 += s[ng][0] + s[ng][1];
            rs1 += s[ng][2] + s[ng][3];
        }
        rs0 += __shfl_xor_sync(0xffffffffu, rs0, 1);
        rs0 += __shfl_xor_sync(0xffffffffu, rs0, 2);
        rs1 += __shfl_xor_sync(0xffffffffu, rs1, 1);
        rs1 += __shfl_xor_sync(0xffffffffu, rs1, 2);

        l[0] = l[0] * sc0 + rs0;  m[0] = mn0;
        l[1] = l[1] * sc1 + rs1;  m[1] = mn1;
#pragma unroll
        for (int ng = 0; ng < 8; ++ng) {
            o[ng][0] *= sc0; o[ng][1] *= sc0;
            o[ng][2] *= sc1; o[ng][3] *= sc1;
        }

        // ---- O += P V (P from regs, split bf16, 3 MMAs) ----
#pragma unroll
        for (int ks = 0; ks < 4; ++ks) {
            float* sa = s[2 * ks];
            float* sc = s[2 * ks + 1];
            uint32_t ph0 = packbf(sa[0], sa[1]);
            uint32_t ph1 = packbf(sa[2], sa[3]);
            uint32_t ph2 = packbf(sc[0], sc[1]);
            uint32_t ph3 = packbf(sc[2], sc[3]);
            uint32_t pl0 = packbf(bfres(sa[0]), bfres(sa[1]));
            uint32_t pl1 = packbf(bfres(sa[2]), bfres(sa[3]));
            uint32_t pl2 = packbf(bfres(sc[0]), bfres(sc[1]));
            uint32_t pl3 = packbf(bfres(sc[2]), bfres(sc[3]));
#pragma unroll
            for (int p = 0; p < 4; ++p) {
                uint32_t vh0, vh1, vh2, vh3, vl0, vl1, vl2, vl3;
                LDSM4(vh0, vh1, vh2, vh3,
                      sVh32 + boff + p * (16 * 72 * 2) + ks * 32);
                LDSM4(vl0, vl1, vl2, vl3,
                      sVl32 + boff + p * (16 * 72 * 2) + ks * 32);
                MMA16816(o[2*p],   ph0, ph1, ph2, ph3, vh0, vh1);
                MMA16816(o[2*p],   ph0, ph1, ph2, ph3, vl0, vl1);
                MMA16816(o[2*p],   pl0, pl1, pl2, pl3, vh0, vh1);
                MMA16816(o[2*p+1], ph0, ph1, ph2, ph3, vh2, vh3);
                MMA16816(o[2*p+1], ph0, ph1, ph2, ph3, vl2, vl3);
                MMA16816(o[2*p+1], pl0, pl1, pl2, pl3, vh2, vh3);
            }
        }
    }

    // epilogue
    float inv0 = 1.f / l[0], inv1 = 1.f / l[1];
    float* row0 = g_conc + ((size_t)b * LQ + q0 + mw + r) * 512 + hh * 64;
    float* row1 = row0 + 8 * 512;
#pragma unroll
    for (int ng = 0; ng < 8; ++ng) {
        *(float2*)(row0 + ng * 8 + cg) = make_float2(o[ng][0] * inv0, o[ng][1] * inv0);
        *(float2*)(row1 + ng * 8 + cg) = make_float2(o[ng][2] * inv1, o[ng][3] * inv1);
    }
}

// ---------------------------------------------------------------------------
// LayerNorm over last dim (512)
// ---------------------------------------------------------------------------
__global__ __launch_bounds__(128) void ln_kernel(
    const float* __restrict__ gamma, const float* __restrict__ beta,
    float* __restrict__ out)
{
    const int row = blockIdx.x;
    const float* x = g_conc + (size_t)row * 512;
    const int tid = threadIdx.x;

    float v[4];
    float s = 0.f;
#pragma unroll
    for (int i = 0; i < 4; ++i) { v[i] = x[tid + i * 128]; s += v[i]; }

    __shared__ float red1[4];
    __shared__ float red2[4];
#pragma unroll
    for (int off = 16; off >= 1; off >>= 1)
        s += __shfl_xor_sync(0xffffffffu, s, off);
    if ((tid & 31) == 0) red1[tid >> 5] = s;
    __syncthreads();
    float mean = (red1[0] + red1[1] + red1[2] + red1[3]) * (1.f / 512.f);

    float q = 0.f;
#pragma unroll
    for (int i = 0; i < 4; ++i) { float d = v[i] - mean; q += d * d; }
#pragma unroll
    for (int off = 16; off >= 1; off >>= 1)
        q += __shfl_xor_sync(0xffffffffu, q, off);
    if ((tid & 31) == 0) red2[tid >> 5] = q;
    __syncthreads();
    float var  = (red2[0] + red2[1] + red2[2] + red2[3]) * (1.f / 512.f);
    float rstd = rsqrtf(var + 1e-14f);
    float g = gamma[0], be = beta[0];
#pragma unroll
    for (int i = 0; i < 4; ++i)
        out[(size_t)row * 512 + tid + i * 128] = (v[i] - mean) * rstd * g + be;
}

// ---------------------------------------------------------------------------
extern "C" void kernel_launch(void* const* d_in, const int* in_sizes, int n_in,
                              void* d_out, int out_size)
{
    const float* query = (const float*)d_in[0];
    const float* key_t = (const float*)d_in[1];
    const float* value = (const float*)d_in[2];
    const float* mask  = (const float*)d_in[3];
    const float* Wq    = (const float*)d_in[4];
    const float* Wk    = (const float*)d_in[5];
    const float* Wv    = (const float*)d_in[6];
    const float* gamma = (const float*)d_in[7];
    const float* beta  = (const float*)d_in[8];
    float* out = (float*)d_out;

    static int attr_set = 0;
    if (!attr_set) {
        cudaFuncSetAttribute(proj_mma_kernel,
                             cudaFuncAttributeMaxDynamicSharedMemorySize, PROJ_SMEM);
        cudaFuncSetAttribute(attn_mma_kernel,
                             cudaFuncAttributeMaxDynamicSharedMemorySize, ATTN_SMEM);
        attr_set = 1;
    }

    convert_x_kernel<<<dim3(4096, 3), 256>>>(query, key_t, value);
    convert_w_kernel<<<dim3(3, 8), 256>>>(Wq, Wk, Wv);

    proj_mma_kernel<<<dim3(LQ / 128, H, 3 * B), 256, PROJ_SMEM>>>();
    vt_kernel<<<dim3(32, 2, 64), dim3(32, 8)>>>();

    attn_mma_kernel<<<dim3(LQ / 128, B * H), 256, ATTN_SMEM>>>(mask);

    ln_kernel<<<B * LQ, 128>>>(gamma, beta, out);
}

// round 7
// speedup vs baseline: 1.5135x; 1.5135x over previous
#include <cuda_runtime.h>
#include <cuda_bf16.h>
#include <math.h>
#include <stdint.h>

#define B   8
#define LQ  1024
#define LK  1024
#define DD  512
#define H   8

// ---------------------------------------------------------------------------
// Device scratch (static globals — allocation-guard safe)
// ---------------------------------------------------------------------------
#define XN (8ull*1024*512)
__device__ __nv_bfloat16 g_xh[3*XN];               // inputs hi
__device__ __nv_bfloat16 g_xl[3*XN];               // inputs lo
__device__ __nv_bfloat16 g_wth[3ull*8*64*512];     // W^T hi [which][h][e][d]
__device__ __nv_bfloat16 g_wtl[3ull*8*64*512];     // W^T lo
__device__ __nv_bfloat16 g_oh[3ull*64*1024*64];    // proj out hi [which][bh][l][e]
__device__ __nv_bfloat16 g_ol[3ull*64*1024*64];    // proj out lo
__device__ __nv_bfloat16 g_vth[64ull*64*1024];     // V^T hi [bh][e][l]
__device__ __nv_bfloat16 g_vtl[64ull*64*1024];     // V^T lo
__device__ float g_conc[(size_t)B*LQ*512];

// ---------------------------------------------------------------------------
// mma.sync m16n8k16 bf16 (row.col), f32 accum; cp.async helpers
// ---------------------------------------------------------------------------
#define MMA16816(c, a0, a1, a2, a3, b0, b1)                                   \
    asm volatile(                                                             \
        "mma.sync.aligned.m16n8k16.row.col.f32.bf16.bf16.f32 "                \
        "{%0,%1,%2,%3}, {%4,%5,%6,%7}, {%8,%9}, {%0,%1,%2,%3};"               \
        : "+f"((c)[0]), "+f"((c)[1]), "+f"((c)[2]), "+f"((c)[3])              \
        : "r"(a0), "r"(a1), "r"(a2), "r"(a3), "r"(b0), "r"(b1))

__device__ __forceinline__ void cp16(uint32_t dst, const void* src) {
    asm volatile("cp.async.cg.shared.global [%0], [%1], 16;"
                 :: "r"(dst), "l"(src));
}
#define CP_COMMIT() asm volatile("cp.async.commit_group;")
#define CP_WAIT1()  asm volatile("cp.async.wait_group 1;" ::: "memory")
#define CP_WAIT0()  asm volatile("cp.async.wait_group 0;" ::: "memory")

__device__ __forceinline__ uint32_t smem_u32(const void* p) {
    uint32_t a;
    asm("{ .reg .u64 t; cvta.to.shared.u64 t, %1; cvt.u32.u64 %0, t; }"
        : "=r"(a) : "l"(p));
    return a;
}
__device__ __forceinline__ uint32_t packbf(float lo, float hi) {
    uint32_t d;
    asm("cvt.rn.bf16x2.f32 %0, %1, %2;" : "=r"(d) : "f"(hi), "f"(lo));
    return d;
}
__device__ __forceinline__ float bfres(float x) {
    return x - __bfloat162float(__float2bfloat16_rn(x));
}

// ---------------------------------------------------------------------------
// Convert inputs fp32 -> bf16 hi/lo
// ---------------------------------------------------------------------------
__global__ __launch_bounds__(256) void convert_x_kernel(
    const float* __restrict__ q, const float* __restrict__ k,
    const float* __restrict__ v)
{
    const int which = blockIdx.y;
    const float* src = (which == 0) ? q : (which == 1) ? k : v;
    size_t i4 = (size_t)blockIdx.x * 256 + threadIdx.x;
    float4 x = ((const float4*)src)[i4];
    size_t base = (size_t)which * XN + i4 * 4;

    __nv_bfloat16 h0 = __float2bfloat16(x.x);
    __nv_bfloat16 h1 = __float2bfloat16(x.y);
    __nv_bfloat16 h2 = __float2bfloat16(x.z);
    __nv_bfloat16 h3 = __float2bfloat16(x.w);
    ((__nv_bfloat162*)(g_xh + base))[0] = __halves2bfloat162(h0, h1);
    ((__nv_bfloat162*)(g_xh + base))[1] = __halves2bfloat162(h2, h3);
    ((__nv_bfloat162*)(g_xl + base))[0] = __halves2bfloat162(
        __float2bfloat16(x.x - __bfloat162float(h0)),
        __float2bfloat16(x.y - __bfloat162float(h1)));
    ((__nv_bfloat162*)(g_xl + base))[1] = __halves2bfloat162(
        __float2bfloat16(x.z - __bfloat162float(h2)),
        __float2bfloat16(x.w - __bfloat162float(h3)));
}

// ---------------------------------------------------------------------------
// Convert + transpose weights: W[h][d][e] fp32 -> g_wt{h,l}[which][h][e][d]
// ---------------------------------------------------------------------------
__global__ __launch_bounds__(256) void convert_w_kernel(
    const float* __restrict__ Wq, const float* __restrict__ Wk,
    const float* __restrict__ Wv)
{
    const int which = blockIdx.x;
    const int h     = blockIdx.y;
    const float* W = ((which == 0) ? Wq : (which == 1) ? Wk : Wv) + (size_t)h * DD * 64;
    size_t obase = ((size_t)(which * 8 + h)) * 64 * 512;
    for (int it = 0; it < 128; ++it) {
        int idx = it * 256 + threadIdx.x;
        int e = idx & 63, d = idx >> 6;
        float x = W[(size_t)d * 64 + e];
        __nv_bfloat16 hi = __float2bfloat16(x);
        g_wth[obase + (size_t)e * 512 + d] = hi;
        g_wtl[obase + (size_t)e * 512 + d] =
            __float2bfloat16(x - __bfloat162float(hi));
    }
}

// ---------------------------------------------------------------------------
// Projection via mma.sync, double-buffered cp.async.
// grid (LQ/128, H, 3*B), 256 threads. Stage (elems): Ah 0, Al 9216,
// Bh 18432, Bl 23040; stage size 27648 elems; two stages.
// ---------------------------------------------------------------------------
#define PSTG 27648
#define PROJ_SMEM (2 * PSTG * 2)   // 110592 bytes

__device__ __forceinline__ void proj_load_stage(
    const __nv_bfloat16* xh, const __nv_bfloat16* xl,
    const __nv_bfloat16* wh, const __nv_bfloat16* wl,
    uint32_t sb32, int stage, int dt, int tid)
{
    uint32_t base = sb32 + (stage ? PSTG * 2 : 0);
#pragma unroll
    for (int rr = 0; rr < 4; ++rr) {
        int u = tid + rr * 256;
        int row = u >> 3, c8 = (u & 7) * 8;
        uint32_t d = base + (row * 72 + c8) * 2;
        const size_t so = (size_t)row * 512 + dt * 64 + c8;
        cp16(d,            xh + so);
        cp16(d + 9216 * 2, xl + so);
    }
#pragma unroll
    for (int rr = 0; rr < 2; ++rr) {
        int u = tid + rr * 256;
        int e = u >> 3, c8 = (u & 7) * 8;
        uint32_t d = base + (18432 + e * 72 + c8) * 2;
        const size_t so = (size_t)e * 512 + dt * 64 + c8;
        cp16(d,            wh + so);
        cp16(d + 4608 * 2, wl + so);
    }
}

__global__ __launch_bounds__(256, 2) void proj_mma_kernel()
{
    extern __shared__ __nv_bfloat16 psm[];

    const int tid  = threadIdx.x;
    const int warp = tid >> 5;
    const int lane = tid & 31;
    const int r    = lane >> 2;
    const int cg   = (lane & 3) * 2;
    const int mw   = warp * 16;

    const int l0 = blockIdx.x * 128;
    const int h  = blockIdx.y;
    const int z  = blockIdx.z;
    const int which = z >> 3, b = z & 7;

    const __nv_bfloat16* xh = g_xh + (size_t)which * XN + ((size_t)b * 1024 + l0) * 512;
    const __nv_bfloat16* xl = g_xl + (size_t)which * XN + ((size_t)b * 1024 + l0) * 512;
    const __nv_bfloat16* wh = g_wth + ((size_t)(which * 8 + h)) * 64 * 512;
    const __nv_bfloat16* wl = g_wtl + ((size_t)(which * 8 + h)) * 64 * 512;

    const uint32_t sb32 = smem_u32(psm);

    float c[8][4];
#pragma unroll
    for (int n = 0; n < 8; ++n)
#pragma unroll
        for (int j = 0; j < 4; ++j) c[n][j] = 0.f;

    proj_load_stage(xh, xl, wh, wl, sb32, 0, 0, tid);
    CP_COMMIT();

    for (int dt = 0; dt < 8; ++dt) {
        if (dt + 1 < 8) {
            proj_load_stage(xh, xl, wh, wl, sb32, (dt + 1) & 1, dt + 1, tid);
            CP_COMMIT();
            CP_WAIT1();
        } else {
            CP_WAIT0();
        }
        __syncthreads();

        const __nv_bfloat16* pS = psm + ((dt & 1) ? PSTG : 0);
        const __nv_bfloat16* sAh = pS;
        const __nv_bfloat16* sAl = pS + 9216;
        const __nv_bfloat16* sBh = pS + 18432;
        const __nv_bfloat16* sBl = pS + 23040;

#pragma unroll
        for (int ks = 0; ks < 4; ++ks) {
            int ro = (mw + r) * 72 + ks * 16 + cg;
            uint32_t ah0 = *(const uint32_t*)(sAh + ro);
            uint32_t ah1 = *(const uint32_t*)(sAh + ro + 8 * 72);
            uint32_t ah2 = *(const uint32_t*)(sAh + ro + 8);
            uint32_t ah3 = *(const uint32_t*)(sAh + ro + 8 * 72 + 8);
            uint32_t al0 = *(const uint32_t*)(sAl + ro);
            uint32_t al1 = *(const uint32_t*)(sAl + ro + 8 * 72);
            uint32_t al2 = *(const uint32_t*)(sAl + ro + 8);
            uint32_t al3 = *(const uint32_t*)(sAl + ro + 8 * 72 + 8);
#pragma unroll
            for (int n = 0; n < 8; ++n) {
                int bo = (n * 8 + r) * 72 + ks * 16 + cg;
                uint32_t bh0 = *(const uint32_t*)(sBh + bo);
                uint32_t bh1 = *(const uint32_t*)(sBh + bo + 8);
                uint32_t bl0 = *(const uint32_t*)(sBl + bo);
                uint32_t bl1 = *(const uint32_t*)(sBl + bo + 8);
                MMA16816(c[n], ah0, ah1, ah2, ah3, bh0, bh1);
                MMA16816(c[n], ah0, ah1, ah2, ah3, bl0, bl1);
                MMA16816(c[n], al0, al1, al2, al3, bh0, bh1);
            }
        }
        __syncthreads();
    }

    size_t rowbase = ((size_t)(which * 64 + b * 8 + h) * 1024 + l0 + mw + r) * 64;
#pragma unroll
    for (int n = 0; n < 8; ++n) {
        *(uint32_t*)(g_oh + rowbase + n * 8 + cg) = packbf(c[n][0], c[n][1]);
        *(uint32_t*)(g_ol + rowbase + n * 8 + cg) =
            packbf(bfres(c[n][0]), bfres(c[n][1]));
        *(uint32_t*)(g_oh + rowbase + 8 * 64 + n * 8 + cg) = packbf(c[n][2], c[n][3]);
        *(uint32_t*)(g_ol + rowbase + 8 * 64 + n * 8 + cg) =
            packbf(bfres(c[n][2]), bfres(c[n][3]));
    }
}

// ---------------------------------------------------------------------------
// Transpose V hi/lo: g_oh/g_ol[2][bh][l][e] -> g_vth/g_vtl[bh][e][l]
// ---------------------------------------------------------------------------
__global__ __launch_bounds__(256) void vt_kernel()
{
    __shared__ __nv_bfloat16 t[32][33];
    const int bh = blockIdx.z;
    const int l0 = blockIdx.x * 32;
    const int e0 = blockIdx.y * 32;
    const int x = threadIdx.x, y = threadIdx.y;

    const __nv_bfloat16* srch = g_oh + ((size_t)(2 * 64 + bh) * 1024) * 64;
    const __nv_bfloat16* srcl = g_ol + ((size_t)(2 * 64 + bh) * 1024) * 64;
    __nv_bfloat16* dsth = g_vth + (size_t)bh * 64 * 1024;
    __nv_bfloat16* dstl = g_vtl + (size_t)bh * 64 * 1024;

#pragma unroll
    for (int rr = 0; rr < 4; ++rr)
        t[y + 8 * rr][x] = srch[(size_t)(l0 + y + 8 * rr) * 64 + e0 + x];
    __syncthreads();
#pragma unroll
    for (int rr = 0; rr < 4; ++rr)
        dsth[(size_t)(e0 + y + 8 * rr) * 1024 + l0 + x] = t[x][y + 8 * rr];
    __syncthreads();
#pragma unroll
    for (int rr = 0; rr < 4; ++rr)
        t[y + 8 * rr][x] = srcl[(size_t)(l0 + y + 8 * rr) * 64 + e0 + x];
    __syncthreads();
#pragma unroll
    for (int rr = 0; rr < 4; ++rr)
        dstl[(size_t)(e0 + y + 8 * rr) * 1024 + l0 + x] = t[x][y + 8 * rr];
}

// ---------------------------------------------------------------------------
// Flash attention via mma.sync, double-buffered cp.async K/V tiles.
// Layout (elems): Qh 0, Ql 9216; stage0 @18432, stage1 @36864
// (within stage: Kh 0, Kl 4608, Vh 9216, Vl 13824); masks @byte 110592.
// ---------------------------------------------------------------------------
#define OQH 0
#define OQL 9216
#define ASTG0 18432
#define ASTG1 36864
#define AMSK_BYTES 110592
#define ATTN_SMEM (110592 + 512)

__device__ __forceinline__ void attn_load_stage(
    const __nv_bfloat16* Kh, const __nv_bfloat16* Kl,
    const __nv_bfloat16* Vth, const __nv_bfloat16* Vtl,
    const float* msrc, uint32_t sb32, int stage, int kt, int tid)
{
    uint32_t base = sb32 + (stage ? ASTG1 : ASTG0) * 2;
#pragma unroll
    for (int rr = 0; rr < 2; ++rr) {
        int u = tid + rr * 256;
        int row = u >> 3, c8 = (u & 7) * 8;
        uint32_t d = base + (row * 72 + c8) * 2;
        const size_t ko = (size_t)(kt * 64 + row) * 64 + c8;
        const size_t vo = (size_t)row * 1024 + kt * 64 + c8;
        cp16(d,             Kh + ko);
        cp16(d + 4608 * 2,  Kl + ko);
        cp16(d + 9216 * 2,  Vth + vo);
        cp16(d + 13824 * 2, Vtl + vo);
    }
    if (tid < 16)
        cp16(sb32 + AMSK_BYTES + stage * 256 + tid * 16, msrc + kt * 64 + tid * 4);
}

__global__ __launch_bounds__(256, 2) void attn_mma_kernel(const float* __restrict__ mask)
{
    extern __shared__ __nv_bfloat16 sb[];
    __nv_bfloat16* sQh = sb + OQH;   // [128][72]
    __nv_bfloat16* sQl = sb + OQL;

    const int tid  = threadIdx.x;
    const int warp = tid >> 5;
    const int lane = tid & 31;
    const int r    = lane >> 2;
    const int cg   = (lane & 3) * 2;
    const int mw   = warp * 16;

    const int q0 = blockIdx.x * 128;
    const int bh = blockIdx.y;
    const int b  = bh >> 3;
    const int hh = bh & 7;

    const __nv_bfloat16* Qh = g_oh + ((size_t)(0 * 64 + bh) * 1024 + q0) * 64;
    const __nv_bfloat16* Ql = g_ol + ((size_t)(0 * 64 + bh) * 1024 + q0) * 64;
    const __nv_bfloat16* Kh = g_oh + ((size_t)(1 * 64 + bh) * 1024) * 64;
    const __nv_bfloat16* Kl = g_ol + ((size_t)(1 * 64 + bh) * 1024) * 64;
    const __nv_bfloat16* Vth = g_vth + (size_t)bh * 64 * 1024;
    const __nv_bfloat16* Vtl = g_vtl + (size_t)bh * 64 * 1024;
    const float* msrc = mask + (size_t)b * LK;

    const uint32_t sb32 = smem_u32(sb);

    // prefetch first K/V stage, then stage Q with regular loads (overlaps)
    attn_load_stage(Kh, Kl, Vth, Vtl, msrc, sb32, 0, 0, tid);
    CP_COMMIT();

#pragma unroll
    for (int rr = 0; rr < 4; ++rr) {
        int u = tid + rr * 256;
        int row = u >> 3, c8 = (u & 7) * 8;
        *(uint4*)(sQh + row * 72 + c8) = *(const uint4*)(Qh + (size_t)row * 64 + c8);
        *(uint4*)(sQl + row * 72 + c8) = *(const uint4*)(Ql + (size_t)row * 64 + c8);
    }

    float m[2], l[2], o[8][4];
    m[0] = m[1] = -1e30f;
    l[0] = l[1] = 0.f;
#pragma unroll
    for (int n = 0; n < 8; ++n)
#pragma unroll
        for (int j = 0; j < 4; ++j) o[n][j] = 0.f;

    for (int kt = 0; kt < 16; ++kt) {
        if (kt + 1 < 16) {
            attn_load_stage(Kh, Kl, Vth, Vtl, msrc, sb32, (kt + 1) & 1, kt + 1, tid);
            CP_COMMIT();
            CP_WAIT1();
        } else {
            CP_WAIT0();
        }
        __syncthreads();

        const int cur = kt & 1;
        const __nv_bfloat16* bS = sb + (cur ? ASTG1 : ASTG0);
        const __nv_bfloat16* sKh = bS;
        const __nv_bfloat16* sKl = bS + 4608;
        const __nv_bfloat16* sVh = bS + 9216;
        const __nv_bfloat16* sVl = bS + 13824;
        const float* smask = (const float*)((const char*)sb + AMSK_BYTES + cur * 256);

        // ---- S = Q K^T (split bf16, 3 MMAs) ----
        float s[8][4];
#pragma unroll
        for (int n = 0; n < 8; ++n)
#pragma unroll
            for (int j = 0; j < 4; ++j) s[n][j] = 0.f;

#pragma unroll
        for (int ks = 0; ks < 4; ++ks) {
            int ro = (mw + r) * 72 + ks * 16 + cg;
            uint32_t qh0 = *(const uint32_t*)(sQh + ro);
            uint32_t qh1 = *(const uint32_t*)(sQh + ro + 8 * 72);
            uint32_t qh2 = *(const uint32_t*)(sQh + ro + 8);
            uint32_t qh3 = *(const uint32_t*)(sQh + ro + 8 * 72 + 8);
            uint32_t ql0 = *(const uint32_t*)(sQl + ro);
            uint32_t ql1 = *(const uint32_t*)(sQl + ro + 8 * 72);
            uint32_t ql2 = *(const uint32_t*)(sQl + ro + 8);
            uint32_t ql3 = *(const uint32_t*)(sQl + ro + 8 * 72 + 8);
#pragma unroll
            for (int ng = 0; ng < 8; ++ng) {
                int bo = (ng * 8 + r) * 72 + ks * 16 + cg;
                uint32_t kh0 = *(const uint32_t*)(sKh + bo);
                uint32_t kh1 = *(const uint32_t*)(sKh + bo + 8);
                uint32_t kl0 = *(const uint32_t*)(sKl + bo);
                uint32_t kl1 = *(const uint32_t*)(sKl + bo + 8);
                MMA16816(s[ng], qh0, qh1, qh2, qh3, kh0, kh1);
                MMA16816(s[ng], qh0, qh1, qh2, qh3, kl0, kl1);
                MMA16816(s[ng], ql0, ql1, ql2, ql3, kh0, kh1);
            }
        }

        // ---- mask ----
#pragma unroll
        for (int ng = 0; ng < 8; ++ng) {
            float mk0 = smask[ng * 8 + cg];
            float mk1 = smask[ng * 8 + cg + 1];
            if (mk0 == 0.f) { s[ng][0] = -1e30f; s[ng][2] = -1e30f; }
            if (mk1 == 0.f) { s[ng][1] = -1e30f; s[ng][3] = -1e30f; }
        }

        // ---- online softmax on fragments ----
        float rm0 = -1e30f, rm1 = -1e30f;
#pragma unroll
        for (int ng = 0; ng < 8; ++ng) {
            rm0 = fmaxf(rm0, fmaxf(s[ng][0], s[ng][1]));
            rm1 = fmaxf(rm1, fmaxf(s[ng][2], s[ng][3]));
        }
        rm0 = fmaxf(rm0, __shfl_xor_sync(0xffffffffu, rm0, 1));
        rm0 = fmaxf(rm0, __shfl_xor_sync(0xffffffffu, rm0, 2));
        rm1 = fmaxf(rm1, __shfl_xor_sync(0xffffffffu, rm1, 1));
        rm1 = fmaxf(rm1, __shfl_xor_sync(0xffffffffu, rm1, 2));

        float mn0 = fmaxf(m[0], rm0), mn1 = fmaxf(m[1], rm1);
        float sc0 = __expf(m[0] - mn0), sc1 = __expf(m[1] - mn1);
        float rs0 = 0.f, rs1 = 0.f;
#pragma unroll
        for (int ng = 0; ng < 8; ++ng) {
            s[ng][0] = __expf(s[ng][0] - mn0);
            s[ng][1] = __expf(s[ng][1] - mn0);
            s[ng][2] = __expf(s[ng][2] - mn1);
            s[ng][3] = __expf(s[ng][3] - mn1);
            rs0 += s[ng][0] + s[ng][1];
            rs1 += s[ng][2] + s[ng][3];
        }
        rs0 += __shfl_xor_sync(0xffffffffu, rs0, 1);
        rs0 += __shfl_xor_sync(0xffffffffu, rs0, 2);
        rs1 += __shfl_xor_sync(0xffffffffu, rs1, 1);
        rs1 += __shfl_xor_sync(0xffffffffu, rs1, 2);

        l[0] = l[0] * sc0 + rs0;  m[0] = mn0;
        l[1] = l[1] * sc1 + rs1;  m[1] = mn1;
#pragma unroll
        for (int ng = 0; ng < 8; ++ng) {
            o[ng][0] *= sc0; o[ng][1] *= sc0;
            o[ng][2] *= sc1; o[ng][3] *= sc1;
        }

        // ---- O += P V (P from regs, split bf16, 3 MMAs) ----
#pragma unroll
        for (int ks = 0; ks < 4; ++ks) {
            float* sa = s[2 * ks];
            float* sc = s[2 * ks + 1];
            uint32_t ph0 = packbf(sa[0], sa[1]);
            uint32_t ph1 = packbf(sa[2], sa[3]);
            uint32_t ph2 = packbf(sc[0], sc[1]);
            uint32_t ph3 = packbf(sc[2], sc[3]);
            uint32_t pl0 = packbf(bfres(sa[0]), bfres(sa[1]));
            uint32_t pl1 = packbf(bfres(sa[2]), bfres(sa[3]));
            uint32_t pl2 = packbf(bfres(sc[0]), bfres(sc[1]));
            uint32_t pl3 = packbf(bfres(sc[2]), bfres(sc[3]));
#pragma unroll
            for (int ng = 0; ng < 8; ++ng) {
                int bo = (ng * 8 + r) * 72 + ks * 16 + cg;
                uint32_t vh0 = *(const uint32_t*)(sVh + bo);
                uint32_t vh1 = *(const uint32_t*)(sVh + bo + 8);
                uint32_t vl0 = *(const uint32_t*)(sVl + bo);
                uint32_t vl1 = *(const uint32_t*)(sVl + bo + 8);
                MMA16816(o[ng], ph0, ph1, ph2, ph3, vh0, vh1);
                MMA16816(o[ng], ph0, ph1, ph2, ph3, vl0, vl1);
                MMA16816(o[ng], pl0, pl1, pl2, pl3, vh0, vh1);
            }
        }
        __syncthreads();
    }

    // epilogue
    float inv0 = 1.f / l[0], inv1 = 1.f / l[1];
    float* row0 = g_conc + ((size_t)b * LQ + q0 + mw + r) * 512 + hh * 64;
    float* row1 = row0 + 8 * 512;
#pragma unroll
    for (int ng = 0; ng < 8; ++ng) {
        *(float2*)(row0 + ng * 8 + cg) = make_float2(o[ng][0] * inv0, o[ng][1] * inv0);
        *(float2*)(row1 + ng * 8 + cg) = make_float2(o[ng][2] * inv1, o[ng][3] * inv1);
    }
}

// ---------------------------------------------------------------------------
// LayerNorm over last dim (512)
// ---------------------------------------------------------------------------
__global__ __launch_bounds__(128) void ln_kernel(
    const float* __restrict__ gamma, const float* __restrict__ beta,
    float* __restrict__ out)
{
    const int row = blockIdx.x;
    const float* x = g_conc + (size_t)row * 512;
    const int tid = threadIdx.x;

    float v[4];
    float s = 0.f;
#pragma unroll
    for (int i = 0; i < 4; ++i) { v[i] = x[tid + i * 128]; s += v[i]; }

    __shared__ float red1[4];
    __shared__ float red2[4];
#pragma unroll
    for (int off = 16; off >= 1; off >>= 1)
        s += __shfl_xor_sync(0xffffffffu, s, off);
    if ((tid & 31) == 0) red1[tid >> 5] = s;
    __syncthreads();
    float mean = (red1[0] + red1[1] + red1[2] + red1[3]) * (1.f / 512.f);

    float q = 0.f;
#pragma unroll
    for (int i = 0; i < 4; ++i) { float d = v[i] - mean; q += d * d; }
#pragma unroll
    for (int off = 16; off >= 1; off >>= 1)
        q += __shfl_xor_sync(0xffffffffu, q, off);
    if ((tid & 31) == 0) red2[tid >> 5] = q;
    __syncthreads();
    float var  = (red2[0] + red2[1] + red2[2] + red2[3]) * (1.f / 512.f);
    float rstd = rsqrtf(var + 1e-14f);
    float g = gamma[0], be = beta[0];
#pragma unroll
    for (int i = 0; i < 4; ++i)
        out[(size_t)row * 512 + tid + i * 128] = (v[i] - mean) * rstd * g + be;
}

// ---------------------------------------------------------------------------
extern "C" void kernel_launch(void* const* d_in, const int* in_sizes, int n_in,
                              void* d_out, int out_size)
{
    const float* query = (const float*)d_in[0];
    const float* key_t = (const float*)d_in[1];
    const float* value = (const float*)d_in[2];
    const float* mask  = (const float*)d_in[3];
    const float* Wq    = (const float*)d_in[4];
    const float* Wk    = (const float*)d_in[5];
    const float* Wv    = (const float*)d_in[6];
    const float* gamma = (const float*)d_in[7];
    const float* beta  = (const float*)d_in[8];
    float* out = (float*)d_out;

    static int attr_set = 0;
    if (!attr_set) {
        cudaFuncSetAttribute(proj_mma_kernel,
                             cudaFuncAttributeMaxDynamicSharedMemorySize, PROJ_SMEM);
        cudaFuncSetAttribute(attn_mma_kernel,
                             cudaFuncAttributeMaxDynamicSharedMemorySize, ATTN_SMEM);
        attr_set = 1;
    }

    convert_x_kernel<<<dim3(4096, 3), 256>>>(query, key_t, value);
    convert_w_kernel<<<dim3(3, 8), 256>>>(Wq, Wk, Wv);

    proj_mma_kernel<<<dim3(LQ / 128, H, 3 * B), 256, PROJ_SMEM>>>();
    vt_kernel<<<dim3(32, 2, 64), dim3(32, 8)>>>();

    attn_mma_kernel<<<dim3(LQ / 128, B * H), 256, ATTN_SMEM>>>(mask);

    ln_kernel<<<B * LQ, 128>>>(gamma, beta, out);
}

// round 8
// speedup vs baseline: 1.5294x; 1.0105x over previous
#include <cuda_runtime.h>
#include <cuda_bf16.h>
#include <math.h>
#include <stdint.h>

#define B   8
#define LQ  1024
#define LK  1024
#define DD  512
#define H   8

// ---------------------------------------------------------------------------
// Device scratch (static globals — allocation-guard safe)
// ---------------------------------------------------------------------------
#define XN (8ull*1024*512)
__device__ __nv_bfloat16 g_xh[3*XN];               // inputs hi
__device__ __nv_bfloat16 g_xl[3*XN];               // inputs lo
__device__ __nv_bfloat16 g_wth[3ull*8*64*512];     // W^T hi [which][h][e][d]
__device__ __nv_bfloat16 g_wtl[3ull*8*64*512];     // W^T lo
__device__ __nv_bfloat16 g_oh[3ull*64*1024*64];    // proj out hi [which][bh][l][e]
__device__ __nv_bfloat16 g_ol[3ull*64*1024*64];    // proj out lo
__device__ __nv_bfloat16 g_vth[64ull*64*1024];     // V^T hi [bh][e][l]
__device__ __nv_bfloat16 g_vtl[64ull*64*1024];     // V^T lo
__device__ float g_conc[(size_t)B*LQ*512];

// ---------------------------------------------------------------------------
// mma.sync m16n8k16 bf16 (row.col), f32 accum; cp.async helpers
// ---------------------------------------------------------------------------
#define MMA16816(c, a0, a1, a2, a3, b0, b1)                                   \
    asm volatile(                                                             \
        "mma.sync.aligned.m16n8k16.row.col.f32.bf16.bf16.f32 "                \
        "{%0,%1,%2,%3}, {%4,%5,%6,%7}, {%8,%9}, {%0,%1,%2,%3};"               \
        : "+f"((c)[0]), "+f"((c)[1]), "+f"((c)[2]), "+f"((c)[3])              \
        : "r"(a0), "r"(a1), "r"(a2), "r"(a3), "r"(b0), "r"(b1))

__device__ __forceinline__ void cp16(uint32_t dst, const void* src) {
    asm volatile("cp.async.cg.shared.global [%0], [%1], 16;"
                 :: "r"(dst), "l"(src));
}
#define CP_COMMIT() asm volatile("cp.async.commit_group;")
#define CP_WAIT1()  asm volatile("cp.async.wait_group 1;" ::: "memory")
#define CP_WAIT0()  asm volatile("cp.async.wait_group 0;" ::: "memory")

__device__ __forceinline__ uint32_t smem_u32(const void* p) {
    uint32_t a;
    asm("{ .reg .u64 t; cvta.to.shared.u64 t, %1; cvt.u32.u64 %0, t; }"
        : "=r"(a) : "l"(p));
    return a;
}
__device__ __forceinline__ uint32_t packbf(float lo, float hi) {
    uint32_t d;
    asm("cvt.rn.bf16x2.f32 %0, %1, %2;" : "=r"(d) : "f"(hi), "f"(lo));
    return d;
}
__device__ __forceinline__ float bfres(float x) {
    return x - __bfloat162float(__float2bfloat16_rn(x));
}

// ---------------------------------------------------------------------------
// Convert inputs fp32 -> bf16 hi/lo
// ---------------------------------------------------------------------------
__global__ __launch_bounds__(256) void convert_x_kernel(
    const float* __restrict__ q, const float* __restrict__ k,
    const float* __restrict__ v)
{
    const int which = blockIdx.y;
    const float* src = (which == 0) ? q : (which == 1) ? k : v;
    size_t i4 = (size_t)blockIdx.x * 256 + threadIdx.x;
    float4 x = ((const float4*)src)[i4];
    size_t base = (size_t)which * XN + i4 * 4;

    __nv_bfloat16 h0 = __float2bfloat16(x.x);
    __nv_bfloat16 h1 = __float2bfloat16(x.y);
    __nv_bfloat16 h2 = __float2bfloat16(x.z);
    __nv_bfloat16 h3 = __float2bfloat16(x.w);
    ((__nv_bfloat162*)(g_xh + base))[0] = __halves2bfloat162(h0, h1);
    ((__nv_bfloat162*)(g_xh + base))[1] = __halves2bfloat162(h2, h3);
    ((__nv_bfloat162*)(g_xl + base))[0] = __halves2bfloat162(
        __float2bfloat16(x.x - __bfloat162float(h0)),
        __float2bfloat16(x.y - __bfloat162float(h1)));
    ((__nv_bfloat162*)(g_xl + base))[1] = __halves2bfloat162(
        __float2bfloat16(x.z - __bfloat162float(h2)),
        __float2bfloat16(x.w - __bfloat162float(h3)));
}

// ---------------------------------------------------------------------------
// Convert + transpose weights: W[h][d][e] fp32 -> g_wt{h,l}[which][h][e][d]
// ---------------------------------------------------------------------------
__global__ __launch_bounds__(256) void convert_w_kernel(
    const float* __restrict__ Wq, const float* __restrict__ Wk,
    const float* __restrict__ Wv)
{
    const int which = blockIdx.x;
    const int h     = blockIdx.y;
    const float* W = ((which == 0) ? Wq : (which == 1) ? Wk : Wv) + (size_t)h * DD * 64;
    size_t obase = ((size_t)(which * 8 + h)) * 64 * 512;
    for (int it = 0; it < 128; ++it) {
        int idx = it * 256 + threadIdx.x;
        int e = idx & 63, d = idx >> 6;
        float x = W[(size_t)d * 64 + e];
        __nv_bfloat16 hi = __float2bfloat16(x);
        g_wth[obase + (size_t)e * 512 + d] = hi;
        g_wtl[obase + (size_t)e * 512 + d] =
            __float2bfloat16(x - __bfloat162float(hi));
    }
}

// ---------------------------------------------------------------------------
// Projection via mma.sync, double-buffered cp.async, term-major MMA issue.
// ---------------------------------------------------------------------------
#define PSTG 27648
#define PROJ_SMEM (2 * PSTG * 2)   // 110592 bytes

__device__ __forceinline__ void proj_load_stage(
    const __nv_bfloat16* xh, const __nv_bfloat16* xl,
    const __nv_bfloat16* wh, const __nv_bfloat16* wl,
    uint32_t sb32, int stage, int dt, int tid)
{
    uint32_t base = sb32 + (stage ? PSTG * 2 : 0);
#pragma unroll
    for (int rr = 0; rr < 4; ++rr) {
        int u = tid + rr * 256;
        int row = u >> 3, c8 = (u & 7) * 8;
        uint32_t d = base + (row * 72 + c8) * 2;
        const size_t so = (size_t)row * 512 + dt * 64 + c8;
        cp16(d,            xh + so);
        cp16(d + 9216 * 2, xl + so);
    }
#pragma unroll
    for (int rr = 0; rr < 2; ++rr) {
        int u = tid + rr * 256;
        int e = u >> 3, c8 = (u & 7) * 8;
        uint32_t d = base + (18432 + e * 72 + c8) * 2;
        const size_t so = (size_t)e * 512 + dt * 64 + c8;
        cp16(d,            wh + so);
        cp16(d + 4608 * 2, wl + so);
    }
}

__global__ __launch_bounds__(256, 2) void proj_mma_kernel()
{
    extern __shared__ __nv_bfloat16 psm[];

    const int tid  = threadIdx.x;
    const int warp = tid >> 5;
    const int lane = tid & 31;
    const int r    = lane >> 2;
    const int cg   = (lane & 3) * 2;
    const int mw   = warp * 16;

    const int l0 = blockIdx.x * 128;
    const int h  = blockIdx.y;
    const int z  = blockIdx.z;
    const int which = z >> 3, b = z & 7;

    const __nv_bfloat16* xh = g_xh + (size_t)which * XN + ((size_t)b * 1024 + l0) * 512;
    const __nv_bfloat16* xl = g_xl + (size_t)which * XN + ((size_t)b * 1024 + l0) * 512;
    const __nv_bfloat16* wh = g_wth + ((size_t)(which * 8 + h)) * 64 * 512;
    const __nv_bfloat16* wl = g_wtl + ((size_t)(which * 8 + h)) * 64 * 512;

    const uint32_t sb32 = smem_u32(psm);

    float c[8][4];
#pragma unroll
    for (int n = 0; n < 8; ++n)
#pragma unroll
        for (int j = 0; j < 4; ++j) c[n][j] = 0.f;

    proj_load_stage(xh, xl, wh, wl, sb32, 0, 0, tid);
    CP_COMMIT();

    for (int dt = 0; dt < 8; ++dt) {
        if (dt + 1 < 8) {
            proj_load_stage(xh, xl, wh, wl, sb32, (dt + 1) & 1, dt + 1, tid);
            CP_COMMIT();
            CP_WAIT1();
        } else {
            CP_WAIT0();
        }
        __syncthreads();

        const __nv_bfloat16* pS = psm + ((dt & 1) ? PSTG : 0);
        const __nv_bfloat16* sAh = pS;
        const __nv_bfloat16* sAl = pS + 9216;
        const __nv_bfloat16* sBh = pS + 18432;
        const __nv_bfloat16* sBl = pS + 23040;

#pragma unroll
        for (int ks = 0; ks < 4; ++ks) {
            int ro = (mw + r) * 72 + ks * 16 + cg;
            uint32_t ah0 = *(const uint32_t*)(sAh + ro);
            uint32_t ah1 = *(const uint32_t*)(sAh + ro + 8 * 72);
            uint32_t ah2 = *(const uint32_t*)(sAh + ro + 8);
            uint32_t ah3 = *(const uint32_t*)(sAh + ro + 8 * 72 + 8);
            uint32_t al0 = *(const uint32_t*)(sAl + ro);
            uint32_t al1 = *(const uint32_t*)(sAl + ro + 8 * 72);
            uint32_t al2 = *(const uint32_t*)(sAl + ro + 8);
            uint32_t al3 = *(const uint32_t*)(sAl + ro + 8 * 72 + 8);
#pragma unroll
            for (int hf = 0; hf < 2; ++hf) {
                uint32_t b0[4], b1[4], lb0[4], lb1[4];
#pragma unroll
                for (int j = 0; j < 4; ++j) {
                    int bo = ((hf * 4 + j) * 8 + r) * 72 + ks * 16 + cg;
                    b0[j]  = *(const uint32_t*)(sBh + bo);
                    b1[j]  = *(const uint32_t*)(sBh + bo + 8);
                    lb0[j] = *(const uint32_t*)(sBl + bo);
                    lb1[j] = *(const uint32_t*)(sBl + bo + 8);
                }
#pragma unroll
                for (int j = 0; j < 4; ++j)
                    MMA16816(c[hf*4+j], ah0, ah1, ah2, ah3, b0[j], b1[j]);
#pragma unroll
                for (int j = 0; j < 4; ++j)
                    MMA16816(c[hf*4+j], ah0, ah1, ah2, ah3, lb0[j], lb1[j]);
#pragma unroll
                for (int j = 0; j < 4; ++j)
                    MMA16816(c[hf*4+j], al0, al1, al2, al3, b0[j], b1[j]);
            }
        }
        __syncthreads();
    }

    size_t rowbase = ((size_t)(which * 64 + b * 8 + h) * 1024 + l0 + mw + r) * 64;
#pragma unroll
    for (int n = 0; n < 8; ++n) {
        *(uint32_t*)(g_oh + rowbase + n * 8 + cg) = packbf(c[n][0], c[n][1]);
        *(uint32_t*)(g_ol + rowbase + n * 8 + cg) =
            packbf(bfres(c[n][0]), bfres(c[n][1]));
        *(uint32_t*)(g_oh + rowbase + 8 * 64 + n * 8 + cg) = packbf(c[n][2], c[n][3]);
        *(uint32_t*)(g_ol + rowbase + 8 * 64 + n * 8 + cg) =
            packbf(bfres(c[n][2]), bfres(c[n][3]));
    }
}

// ---------------------------------------------------------------------------
// Transpose V hi/lo: g_oh/g_ol[2][bh][l][e] -> g_vth/g_vtl[bh][e][l]
// ---------------------------------------------------------------------------
__global__ __launch_bounds__(256) void vt_kernel()
{
    __shared__ __nv_bfloat16 t[32][33];
    const int bh = blockIdx.z;
    const int l0 = blockIdx.x * 32;
    const int e0 = blockIdx.y * 32;
    const int x = threadIdx.x, y = threadIdx.y;

    const __nv_bfloat16* srch = g_oh + ((size_t)(2 * 64 + bh) * 1024) * 64;
    const __nv_bfloat16* srcl = g_ol + ((size_t)(2 * 64 + bh) * 1024) * 64;
    __nv_bfloat16* dsth = g_vth + (size_t)bh * 64 * 1024;
    __nv_bfloat16* dstl = g_vtl + (size_t)bh * 64 * 1024;

#pragma unroll
    for (int rr = 0; rr < 4; ++rr)
        t[y + 8 * rr][x] = srch[(size_t)(l0 + y + 8 * rr) * 64 + e0 + x];
    __syncthreads();
#pragma unroll
    for (int rr = 0; rr < 4; ++rr)
        dsth[(size_t)(e0 + y + 8 * rr) * 1024 + l0 + x] = t[x][y + 8 * rr];
    __syncthreads();
#pragma unroll
    for (int rr = 0; rr < 4; ++rr)
        t[y + 8 * rr][x] = srcl[(size_t)(l0 + y + 8 * rr) * 64 + e0 + x];
    __syncthreads();
#pragma unroll
    for (int rr = 0; rr < 4; ++rr)
        dstl[(size_t)(e0 + y + 8 * rr) * 1024 + l0 + x] = t[x][y + 8 * rr];
}

// ---------------------------------------------------------------------------
// Flash attention via mma.sync, double-buffered cp.async, term-major issue.
// ---------------------------------------------------------------------------
#define OQH 0
#define OQL 9216
#define ASTG0 18432
#define ASTG1 36864
#define AMSK_BYTES 110592
#define ATTN_SMEM (110592 + 512)

__device__ __forceinline__ void attn_load_stage(
    const __nv_bfloat16* Kh, const __nv_bfloat16* Kl,
    const __nv_bfloat16* Vth, const __nv_bfloat16* Vtl,
    const float* msrc, uint32_t sb32, int stage, int kt, int tid)
{
    uint32_t base = sb32 + (stage ? ASTG1 : ASTG0) * 2;
#pragma unroll
    for (int rr = 0; rr < 2; ++rr) {
        int u = tid + rr * 256;
        int row = u >> 3, c8 = (u & 7) * 8;
        uint32_t d = base + (row * 72 + c8) * 2;
        const size_t ko = (size_t)(kt * 64 + row) * 64 + c8;
        const size_t vo = (size_t)row * 1024 + kt * 64 + c8;
        cp16(d,             Kh + ko);
        cp16(d + 4608 * 2,  Kl + ko);
        cp16(d + 9216 * 2,  Vth + vo);
        cp16(d + 13824 * 2, Vtl + vo);
    }
    if (tid < 16)
        cp16(sb32 + AMSK_BYTES + stage * 256 + tid * 16, msrc + kt * 64 + tid * 4);
}

__global__ __launch_bounds__(256, 2) void attn_mma_kernel(const float* __restrict__ mask)
{
    extern __shared__ __nv_bfloat16 sb[];
    __nv_bfloat16* sQh = sb + OQH;   // [128][72]
    __nv_bfloat16* sQl = sb + OQL;

    const int tid  = threadIdx.x;
    const int warp = tid >> 5;
    const int lane = tid & 31;
    const int r    = lane >> 2;
    const int cg   = (lane & 3) * 2;
    const int mw   = warp * 16;

    const int q0 = blockIdx.x * 128;
    const int bh = blockIdx.y;
    const int b  = bh >> 3;
    const int hh = bh & 7;

    const __nv_bfloat16* Qh = g_oh + ((size_t)(0 * 64 + bh) * 1024 + q0) * 64;
    const __nv_bfloat16* Ql = g_ol + ((size_t)(0 * 64 + bh) * 1024 + q0) * 64;
    const __nv_bfloat16* Kh = g_oh + ((size_t)(1 * 64 + bh) * 1024) * 64;
    const __nv_bfloat16* Kl = g_ol + ((size_t)(1 * 64 + bh) * 1024) * 64;
    const __nv_bfloat16* Vth = g_vth + (size_t)bh * 64 * 1024;
    const __nv_bfloat16* Vtl = g_vtl + (size_t)bh * 64 * 1024;
    const float* msrc = mask + (size_t)b * LK;

    const uint32_t sb32 = smem_u32(sb);

    attn_load_stage(Kh, Kl, Vth, Vtl, msrc, sb32, 0, 0, tid);
    CP_COMMIT();

#pragma unroll
    for (int rr = 0; rr < 4; ++rr) {
        int u = tid + rr * 256;
        int row = u >> 3, c8 = (u & 7) * 8;
        *(uint4*)(sQh + row * 72 + c8) = *(const uint4*)(Qh + (size_t)row * 64 + c8);
        *(uint4*)(sQl + row * 72 + c8) = *(const uint4*)(Ql + (size_t)row * 64 + c8);
    }

    float m[2], l[2], o[8][4];
    m[0] = m[1] = -1e30f;
    l[0] = l[1] = 0.f;
#pragma unroll
    for (int n = 0; n < 8; ++n)
#pragma unroll
        for (int j = 0; j < 4; ++j) o[n][j] = 0.f;

    for (int kt = 0; kt < 16; ++kt) {
        if (kt + 1 < 16) {
            attn_load_stage(Kh, Kl, Vth, Vtl, msrc, sb32, (kt + 1) & 1, kt + 1, tid);
            CP_COMMIT();
            CP_WAIT1();
        } else {
            CP_WAIT0();
        }
        __syncthreads();

        const int cur = kt & 1;
        const __nv_bfloat16* bS = sb + (cur ? ASTG1 : ASTG0);
        const __nv_bfloat16* sKh = bS;
        const __nv_bfloat16* sKl = bS + 4608;
        const __nv_bfloat16* sVh = bS + 9216;
        const __nv_bfloat16* sVl = bS + 13824;
        const float* smask = (const float*)((const char*)sb + AMSK_BYTES + cur * 256);

        // ---- S = Q K^T (split bf16, term-major issue) ----
        float s[8][4];
#pragma unroll
        for (int n = 0; n < 8; ++n)
#pragma unroll
            for (int j = 0; j < 4; ++j) s[n][j] = 0.f;

#pragma unroll
        for (int ks = 0; ks < 4; ++ks) {
            int ro = (mw + r) * 72 + ks * 16 + cg;
            uint32_t qh0 = *(const uint32_t*)(sQh + ro);
            uint32_t qh1 = *(const uint32_t*)(sQh + ro + 8 * 72);
            uint32_t qh2 = *(const uint32_t*)(sQh + ro + 8);
            uint32_t qh3 = *(const uint32_t*)(sQh + ro + 8 * 72 + 8);
            uint32_t ql0 = *(const uint32_t*)(sQl + ro);
            uint32_t ql1 = *(const uint32_t*)(sQl + ro + 8 * 72);
            uint32_t ql2 = *(const uint32_t*)(sQl + ro + 8);
            uint32_t ql3 = *(const uint32_t*)(sQl + ro + 8 * 72 + 8);
#pragma unroll
            for (int hf = 0; hf < 2; ++hf) {
                uint32_t b0[4], b1[4], lb0[4], lb1[4];
#pragma unroll
                for (int j = 0; j < 4; ++j) {
                    int bo = ((hf * 4 + j) * 8 + r) * 72 + ks * 16 + cg;
                    b0[j]  = *(const uint32_t*)(sKh + bo);
                    b1[j]  = *(const uint32_t*)(sKh + bo + 8);
                    lb0[j] = *(const uint32_t*)(sKl + bo);
                    lb1[j] = *(const uint32_t*)(sKl + bo + 8);
                }
#pragma unroll
                for (int j = 0; j < 4; ++j)
                    MMA16816(s[hf*4+j], qh0, qh1, qh2, qh3, b0[j], b1[j]);
#pragma unroll
                for (int j = 0; j < 4; ++j)
                    MMA16816(s[hf*4+j], qh0, qh1, qh2, qh3, lb0[j], lb1[j]);
#pragma unroll
                for (int j = 0; j < 4; ++j)
                    MMA16816(s[hf*4+j], ql0, ql1, ql2, ql3, b0[j], b1[j]);
            }
        }

        // ---- mask ----
#pragma unroll
        for (int ng = 0; ng < 8; ++ng) {
            float mk0 = smask[ng * 8 + cg];
            float mk1 = smask[ng * 8 + cg + 1];
            if (mk0 == 0.f) { s[ng][0] = -1e30f; s[ng][2] = -1e30f; }
            if (mk1 == 0.f) { s[ng][1] = -1e30f; s[ng][3] = -1e30f; }
        }

        // ---- online softmax on fragments ----
        float rm0 = -1e30f, rm1 = -1e30f;
#pragma unroll
        for (int ng = 0; ng < 8; ++ng) {
            rm0 = fmaxf(rm0, fmaxf(s[ng][0], s[ng][1]));
            rm1 = fmaxf(rm1, fmaxf(s[ng][2], s[ng][3]));
        }
        rm0 = fmaxf(rm0, __shfl_xor_sync(0xffffffffu, rm0, 1));
        rm0 = fmaxf(rm0, __shfl_xor_sync(0xffffffffu, rm0, 2));
        rm1 = fmaxf(rm1, __shfl_xor_sync(0xffffffffu, rm1, 1));
        rm1 = fmaxf(rm1, __shfl_xor_sync(0xffffffffu, rm1, 2));

        float mn0 = fmaxf(m[0], rm0), mn1 = fmaxf(m[1], rm1);
        float sc0 = __expf(m[0] - mn0), sc1 = __expf(m[1] - mn1);
        float rs0 = 0.f, rs1 = 0.f;
#pragma unroll
        for (int ng = 0; ng < 8; ++ng) {
            s[ng][0] = __expf(s[ng][0] - mn0);
            s[ng][1] = __expf(s[ng][1] - mn0);
            s[ng][2] = __expf(s[ng][2] - mn1);
            s[ng][3] = __expf(s[ng][3] - mn1);
            rs0 += s[ng][0] + s[ng][1];
            rs1 += s[ng][2] + s[ng][3];
        }
        rs0 += __shfl_xor_sync(0xffffffffu, rs0, 1);
        rs0 += __shfl_xor_sync(0xffffffffu, rs0, 2);
        rs1 += __shfl_xor_sync(0xffffffffu, rs1, 1);
        rs1 += __shfl_xor_sync(0xffffffffu, rs1, 2);

        l[0] = l[0] * sc0 + rs0;  m[0] = mn0;
        l[1] = l[1] * sc1 + rs1;  m[1] = mn1;
#pragma unroll
        for (int ng = 0; ng < 8; ++ng) {
            o[ng][0] *= sc0; o[ng][1] *= sc0;
            o[ng][2] *= sc1; o[ng][3] *= sc1;
        }

        // ---- O += P V (P from regs, split bf16, term-major issue) ----
#pragma unroll
        for (int ks = 0; ks < 4; ++ks) {
            float* sa = s[2 * ks];
            float* sc = s[2 * ks + 1];
            uint32_t ph0 = packbf(sa[0], sa[1]);
            uint32_t ph1 = packbf(sa[2], sa[3]);
            uint32_t ph2 = packbf(sc[0], sc[1]);
            uint32_t ph3 = packbf(sc[2], sc[3]);
            uint32_t pl0 = packbf(bfres(sa[0]), bfres(sa[1]));
            uint32_t pl1 = packbf(bfres(sa[2]), bfres(sa[3]));
            uint32_t pl2 = packbf(bfres(sc[0]), bfres(sc[1]));
            uint32_t pl3 = packbf(bfres(sc[2]), bfres(sc[3]));
#pragma unroll
            for (int hf = 0; hf < 2; ++hf) {
                uint32_t v0[4], v1[4], w0[4], w1[4];
#pragma unroll
                for (int j = 0; j < 4; ++j) {
                    int bo = ((hf * 4 + j) * 8 + r) * 72 + ks * 16 + cg;
                    v0[j] = *(const uint32_t*)(sVh + bo);
                    v1[j] = *(const uint32_t*)(sVh + bo + 8);
                    w0[j] = *(const uint32_t*)(sVl + bo);
                    w1[j] = *(const uint32_t*)(sVl + bo + 8);
                }
#pragma unroll
                for (int j = 0; j < 4; ++j)
                    MMA16816(o[hf*4+j], ph0, ph1, ph2, ph3, v0[j], v1[j]);
#pragma unroll
                for (int j = 0; j < 4; ++j)
                    MMA16816(o[hf*4+j], ph0, ph1, ph2, ph3, w0[j], w1[j]);
#pragma unroll
                for (int j = 0; j < 4; ++j)
                    MMA16816(o[hf*4+j], pl0, pl1, pl2, pl3, v0[j], v1[j]);
            }
        }
        __syncthreads();
    }

    // epilogue
    float inv0 = 1.f / l[0], inv1 = 1.f / l[1];
    float* row0 = g_conc + ((size_t)b * LQ + q0 + mw + r) * 512 + hh * 64;
    float* row1 = row0 + 8 * 512;
#pragma unroll
    for (int ng = 0; ng < 8; ++ng) {
        *(float2*)(row0 + ng * 8 + cg) = make_float2(o[ng][0] * inv0, o[ng][1] * inv0);
        *(float2*)(row1 + ng * 8 + cg) = make_float2(o[ng][2] * inv1, o[ng][3] * inv1);
    }
}

// ---------------------------------------------------------------------------
// LayerNorm over last dim (512)
// ---------------------------------------------------------------------------
__global__ __launch_bounds__(128) void ln_kernel(
    const float* __restrict__ gamma, const float* __restrict__ beta,
    float* __restrict__ out)
{
    const int row = blockIdx.x;
    const float* x = g_conc + (size_t)row * 512;
    const int tid = threadIdx.x;

    float v[4];
    float s = 0.f;
#pragma unroll
    for (int i = 0; i < 4; ++i) { v[i] = x[tid + i * 128]; s += v[i]; }

    __shared__ float red1[4];
    __shared__ float red2[4];
#pragma unroll
    for (int off = 16; off >= 1; off >>= 1)
        s += __shfl_xor_sync(0xffffffffu, s, off);
    if ((tid & 31) == 0) red1[tid >> 5] = s;
    __syncthreads();
    float mean = (red1[0] + red1[1] + red1[2] + red1[3]) * (1.f / 512.f);

    float q = 0.f;
#pragma unroll
    for (int i = 0; i < 4; ++i) { float d = v[i] - mean; q += d * d; }
#pragma unroll
    for (int off = 16; off >= 1; off >>= 1)
        q += __shfl_xor_sync(0xffffffffu, q, off);
    if ((tid & 31) == 0) red2[tid >> 5] = q;
    __syncthreads();
    float var  = (red2[0] + red2[1] + red2[2] + red2[3]) * (1.f / 512.f);
    float rstd = rsqrtf(var + 1e-14f);
    float g = gamma[0], be = beta[0];
#pragma unroll
    for (int i = 0; i < 4; ++i)
        out[(size_t)row * 512 + tid + i * 128] = (v[i] - mean) * rstd * g + be;
}

// ---------------------------------------------------------------------------
extern "C" void kernel_launch(void* const* d_in, const int* in_sizes, int n_in,
                              void* d_out, int out_size)
{
    const float* query = (const float*)d_in[0];
    const float* key_t = (const float*)d_in[1];
    const float* value = (const float*)d_in[2];
    const float* mask  = (const float*)d_in[3];
    const float* Wq    = (const float*)d_in[4];
    const float* Wk    = (const float*)d_in[5];
    const float* Wv    = (const float*)d_in[6];
    const float* gamma = (const float*)d_in[7];
    const float* beta  = (const float*)d_in[8];
    float* out = (float*)d_out;

    static int attr_set = 0;
    if (!attr_set) {
        cudaFuncSetAttribute(proj_mma_kernel,
                             cudaFuncAttributeMaxDynamicSharedMemorySize, PROJ_SMEM);
        cudaFuncSetAttribute(attn_mma_kernel,
                             cudaFuncAttributeMaxDynamicSharedMemorySize, ATTN_SMEM);
        attr_set = 1;
    }

    convert_x_kernel<<<dim3(4096, 3), 256>>>(query, key_t, value);
    convert_w_kernel<<<dim3(3, 8), 256>>>(Wq, Wk, Wv);

    proj_mma_kernel<<<dim3(LQ / 128, H, 3 * B), 256, PROJ_SMEM>>>();
    vt_kernel<<<dim3(32, 2, 64), dim3(32, 8)>>>();

    attn_mma_kernel<<<dim3(LQ / 128, B * H), 256, ATTN_SMEM>>>(mask);

    ln_kernel<<<B * LQ, 128>>>(gamma, beta, out);
}

// round 9
// speedup vs baseline: 2.0540x; 1.3431x over previous
#include <cuda_runtime.h>
#include <cuda_bf16.h>
#include <math.h>
#include <stdint.h>

#define B   8
#define LQ  1024
#define LK  1024
#define DD  512
#define H   8

// ---------------------------------------------------------------------------
// Device scratch (static globals — allocation-guard safe)
// ---------------------------------------------------------------------------
#define XN (8ull*1024*512)
__device__ __nv_bfloat16 g_xh[3*XN];               // inputs hi
__device__ __nv_bfloat16 g_xl[3*XN];               // inputs lo
__device__ __nv_bfloat16 g_wth[3ull*8*64*512];     // W^T hi [which][h][e][d]
__device__ __nv_bfloat16 g_wtl[3ull*8*64*512];     // W^T lo
__device__ __nv_bfloat16 g_oh[3ull*64*1024*64];    // proj out hi [which][bh][l][e]
__device__ __nv_bfloat16 g_ol[3ull*64*1024*64];    // proj out lo
__device__ __nv_bfloat16 g_vth[64ull*64*1024];     // V^T hi [bh][e][l]
__device__ __nv_bfloat16 g_vtl[64ull*64*1024];     // V^T lo
__device__ float g_conc[(size_t)B*LQ*512];
// key compaction
__device__ int   g_lidx[B][1024];                  // compacted slot -> source key
__device__ int   g_nlive[B];
__device__ float g_cmask[B][1024];                 // 1 for live slot, 0 for pad

// ---------------------------------------------------------------------------
// mma.sync m16n8k16 bf16 (row.col), f32 accum; cp.async helpers
// ---------------------------------------------------------------------------
#define MMA16816(c, a0, a1, a2, a3, b0, b1)                                   \
    asm volatile(                                                             \
        "mma.sync.aligned.m16n8k16.row.col.f32.bf16.bf16.f32 "                \
        "{%0,%1,%2,%3}, {%4,%5,%6,%7}, {%8,%9}, {%0,%1,%2,%3};"               \
        : "+f"((c)[0]), "+f"((c)[1]), "+f"((c)[2]), "+f"((c)[3])              \
        : "r"(a0), "r"(a1), "r"(a2), "r"(a3), "r"(b0), "r"(b1))

__device__ __forceinline__ void cp16(uint32_t dst, const void* src) {
    asm volatile("cp.async.cg.shared.global [%0], [%1], 16;"
                 :: "r"(dst), "l"(src));
}
#define CP_COMMIT() asm volatile("cp.async.commit_group;")
#define CP_WAIT1()  asm volatile("cp.async.wait_group 1;" ::: "memory")
#define CP_WAIT0()  asm volatile("cp.async.wait_group 0;" ::: "memory")

__device__ __forceinline__ uint32_t smem_u32(const void* p) {
    uint32_t a;
    asm("{ .reg .u64 t; cvta.to.shared.u64 t, %1; cvt.u32.u64 %0, t; }"
        : "=r"(a) : "l"(p));
    return a;
}
__device__ __forceinline__ uint32_t packbf(float lo, float hi) {
    uint32_t d;
    asm("cvt.rn.bf16x2.f32 %0, %1, %2;" : "=r"(d) : "f"(hi), "f"(lo));
    return d;
}
__device__ __forceinline__ float bfres(float x) {
    return x - __bfloat162float(__float2bfloat16_rn(x));
}

// ---------------------------------------------------------------------------
// Key-compaction index build: one block (256 thr) per batch.
// ---------------------------------------------------------------------------
__global__ __launch_bounds__(256) void index_kernel(const float* __restrict__ mask)
{
    const int b   = blockIdx.x;
    const int tid = threadIdx.x;
    __shared__ int wsum[8];
    const float* mb = mask + (size_t)b * 1024;

    int v[4], s = 0;
#pragma unroll
    for (int i = 0; i < 4; ++i) { v[i] = (mb[tid * 4 + i] != 0.f); s += v[i]; }

    const int lane = tid & 31, w = tid >> 5;
    int pre = s;
#pragma unroll
    for (int off = 1; off < 32; off <<= 1) {
        int t = __shfl_up_sync(0xffffffffu, pre, off);
        if (lane >= off) pre += t;
    }
    if (lane == 31) wsum[w] = pre;
    __syncthreads();
    int woff = 0;
    for (int i = 0; i < w; ++i) woff += wsum[i];
    int p = woff + pre - s;
#pragma unroll
    for (int i = 0; i < 4; ++i)
        if (v[i]) g_lidx[b][p++] = tid * 4 + i;
    __syncthreads();
    int total = 0;
    for (int i = 0; i < 8; ++i) total += wsum[i];
    if (tid == 0) g_nlive[b] = total;
    for (int i = tid; i < 1024; i += 256) {
        g_cmask[b][i] = (i < total) ? 1.f : 0.f;
        if (i >= total) g_lidx[b][i] = 0;
    }
}

// ---------------------------------------------------------------------------
// Convert inputs fp32 -> bf16 hi/lo
// ---------------------------------------------------------------------------
__global__ __launch_bounds__(256) void convert_x_kernel(
    const float* __restrict__ q, const float* __restrict__ k,
    const float* __restrict__ v)
{
    const int which = blockIdx.y;
    const float* src = (which == 0) ? q : (which == 1) ? k : v;
    size_t i4 = (size_t)blockIdx.x * 256 + threadIdx.x;
    float4 x = ((const float4*)src)[i4];
    size_t base = (size_t)which * XN + i4 * 4;

    __nv_bfloat16 h0 = __float2bfloat16(x.x);
    __nv_bfloat16 h1 = __float2bfloat16(x.y);
    __nv_bfloat16 h2 = __float2bfloat16(x.z);
    __nv_bfloat16 h3 = __float2bfloat16(x.w);
    ((__nv_bfloat162*)(g_xh + base))[0] = __halves2bfloat162(h0, h1);
    ((__nv_bfloat162*)(g_xh + base))[1] = __halves2bfloat162(h2, h3);
    ((__nv_bfloat162*)(g_xl + base))[0] = __halves2bfloat162(
        __float2bfloat16(x.x - __bfloat162float(h0)),
        __float2bfloat16(x.y - __bfloat162float(h1)));
    ((__nv_bfloat162*)(g_xl + base))[1] = __halves2bfloat162(
        __float2bfloat16(x.z - __bfloat162float(h2)),
        __float2bfloat16(x.w - __bfloat162float(h3)));
}

// ---------------------------------------------------------------------------
// Convert + transpose weights: W[h][d][e] fp32 -> g_wt{h,l}[which][h][e][d]
// ---------------------------------------------------------------------------
__global__ __launch_bounds__(256) void convert_w_kernel(
    const float* __restrict__ Wq, const float* __restrict__ Wk,
    const float* __restrict__ Wv)
{
    const int which = blockIdx.x;
    const int h     = blockIdx.y;
    const float* W = ((which == 0) ? Wq : (which == 1) ? Wk : Wv) + (size_t)h * DD * 64;
    size_t obase = ((size_t)(which * 8 + h)) * 64 * 512;
    for (int it = 0; it < 128; ++it) {
        int idx = it * 256 + threadIdx.x;
        int e = idx & 63, d = idx >> 6;
        float x = W[(size_t)d * 64 + e];
        __nv_bfloat16 hi = __float2bfloat16(x);
        g_wth[obase + (size_t)e * 512 + d] = hi;
        g_wtl[obase + (size_t)e * 512 + d] =
            __float2bfloat16(x - __bfloat162float(hi));
    }
}

// ---------------------------------------------------------------------------
// Projection via mma.sync, double-buffered cp.async, term-major MMA issue.
// K/V (which>=1): X rows gathered via g_lidx (outputs land compacted);
// CTAs past the live-key range exit early.
// ---------------------------------------------------------------------------
#define PSTG 27648
#define PROJ_SMEM (2 * PSTG * 2)   // 110592 bytes

__global__ __launch_bounds__(256, 2) void proj_mma_kernel()
{
    extern __shared__ __nv_bfloat16 psm[];

    const int tid  = threadIdx.x;
    const int warp = tid >> 5;
    const int lane = tid & 31;
    const int r    = lane >> 2;
    const int cg   = (lane & 3) * 2;
    const int mw   = warp * 16;

    const int l0 = blockIdx.x * 128;
    const int h  = blockIdx.y;
    const int z  = blockIdx.z;
    const int which = z >> 3, b = z & 7;

    if (which && l0 >= ((g_nlive[b] + 63) & ~63)) return;

    const __nv_bfloat16* xh = g_xh + (size_t)which * XN + (size_t)b * 1024 * 512;
    const __nv_bfloat16* xl = g_xl + (size_t)which * XN + (size_t)b * 1024 * 512;
    const __nv_bfloat16* wh = g_wth + ((size_t)(which * 8 + h)) * 64 * 512;
    const __nv_bfloat16* wl = g_wtl + ((size_t)(which * 8 + h)) * 64 * 512;

    const uint32_t sb32 = smem_u32(psm);

    // A-row gather sources (constant across dt)
    const int arow = tid >> 3;
    const int c8   = (tid & 7) * 8;
    int asrc[4];
#pragma unroll
    for (int rr = 0; rr < 4; ++rr) {
        int crow = l0 + arow + 32 * rr;
        asrc[rr] = which ? g_lidx[b][crow] : crow;
    }

    float c[8][4];
#pragma unroll
    for (int n = 0; n < 8; ++n)
#pragma unroll
        for (int j = 0; j < 4; ++j) c[n][j] = 0.f;

    // stage loader (A gathered, B natural)
    auto load_stage = [&](int stage, int dt) {
        uint32_t base = sb32 + (stage ? PSTG * 2 : 0);
#pragma unroll
        for (int rr = 0; rr < 4; ++rr) {
            int row = arow + 32 * rr;
            uint32_t d = base + (row * 72 + c8) * 2;
            const size_t so = (size_t)asrc[rr] * 512 + dt * 64 + c8;
            cp16(d,            xh + so);
            cp16(d + 9216 * 2, xl + so);
        }
#pragma unroll
        for (int rr = 0; rr < 2; ++rr) {
            int e = arow + 32 * rr;
            uint32_t d = base + (18432 + e * 72 + c8) * 2;
            const size_t so = (size_t)e * 512 + dt * 64 + c8;
            cp16(d,            wh + so);
            cp16(d + 4608 * 2, wl + so);
        }
    };

    load_stage(0, 0);
    CP_COMMIT();

    for (int dt = 0; dt < 8; ++dt) {
        if (dt + 1 < 8) {
            load_stage((dt + 1) & 1, dt + 1);
            CP_COMMIT();
            CP_WAIT1();
        } else {
            CP_WAIT0();
        }
        __syncthreads();

        const __nv_bfloat16* pS = psm + ((dt & 1) ? PSTG : 0);
        const __nv_bfloat16* sAh = pS;
        const __nv_bfloat16* sAl = pS + 9216;
        const __nv_bfloat16* sBh = pS + 18432;
        const __nv_bfloat16* sBl = pS + 23040;

#pragma unroll
        for (int ks = 0; ks < 4; ++ks) {
            int ro = (mw + r) * 72 + ks * 16 + cg;
            uint32_t ah0 = *(const uint32_t*)(sAh + ro);
            uint32_t ah1 = *(const uint32_t*)(sAh + ro + 8 * 72);
            uint32_t ah2 = *(const uint32_t*)(sAh + ro + 8);
            uint32_t ah3 = *(const uint32_t*)(sAh + ro + 8 * 72 + 8);
            uint32_t al0 = *(const uint32_t*)(sAl + ro);
            uint32_t al1 = *(const uint32_t*)(sAl + ro + 8 * 72);
            uint32_t al2 = *(const uint32_t*)(sAl + ro + 8);
            uint32_t al3 = *(const uint32_t*)(sAl + ro + 8 * 72 + 8);
#pragma unroll
            for (int hf = 0; hf < 2; ++hf) {
                uint32_t b0[4], b1[4], lb0[4], lb1[4];
#pragma unroll
                for (int j = 0; j < 4; ++j) {
                    int bo = ((hf * 4 + j) * 8 + r) * 72 + ks * 16 + cg;
                    b0[j]  = *(const uint32_t*)(sBh + bo);
                    b1[j]  = *(const uint32_t*)(sBh + bo + 8);
                    lb0[j] = *(const uint32_t*)(sBl + bo);
                    lb1[j] = *(const uint32_t*)(sBl + bo + 8);
                }
#pragma unroll
                for (int j = 0; j < 4; ++j)
                    MMA16816(c[hf*4+j], ah0, ah1, ah2, ah3, b0[j], b1[j]);
#pragma unroll
                for (int j = 0; j < 4; ++j)
                    MMA16816(c[hf*4+j], ah0, ah1, ah2, ah3, lb0[j], lb1[j]);
#pragma unroll
                for (int j = 0; j < 4; ++j)
                    MMA16816(c[hf*4+j], al0, al1, al2, al3, b0[j], b1[j]);
            }
        }
        __syncthreads();
    }

    size_t rowbase = ((size_t)(which * 64 + b * 8 + h) * 1024 + l0 + mw + r) * 64;
#pragma unroll
    for (int n = 0; n < 8; ++n) {
        *(uint32_t*)(g_oh + rowbase + n * 8 + cg) = packbf(c[n][0], c[n][1]);
        *(uint32_t*)(g_ol + rowbase + n * 8 + cg) =
            packbf(bfres(c[n][0]), bfres(c[n][1]));
        *(uint32_t*)(g_oh + rowbase + 8 * 64 + n * 8 + cg) = packbf(c[n][2], c[n][3]);
        *(uint32_t*)(g_ol + rowbase + 8 * 64 + n * 8 + cg) =
            packbf(bfres(c[n][2]), bfres(c[n][3]));
    }
}

// ---------------------------------------------------------------------------
// Transpose V hi/lo (compacted): g_oh/g_ol[2][bh][l][e] -> g_vt{h,l}[bh][e][l]
// ---------------------------------------------------------------------------
__global__ __launch_bounds__(256) void vt_kernel()
{
    __shared__ __nv_bfloat16 t[32][33];
    const int bh = blockIdx.z;
    const int l0 = blockIdx.x * 32;
    if (l0 >= ((g_nlive[bh >> 3] + 63) & ~63)) return;
    const int e0 = blockIdx.y * 32;
    const int x = threadIdx.x, y = threadIdx.y;

    const __nv_bfloat16* srch = g_oh + ((size_t)(2 * 64 + bh) * 1024) * 64;
    const __nv_bfloat16* srcl = g_ol + ((size_t)(2 * 64 + bh) * 1024) * 64;
    __nv_bfloat16* dsth = g_vth + (size_t)bh * 64 * 1024;
    __nv_bfloat16* dstl = g_vtl + (size_t)bh * 64 * 1024;

#pragma unroll
    for (int rr = 0; rr < 4; ++rr)
        t[y + 8 * rr][x] = srch[(size_t)(l0 + y + 8 * rr) * 64 + e0 + x];
    __syncthreads();
#pragma unroll
    for (int rr = 0; rr < 4; ++rr)
        dsth[(size_t)(e0 + y + 8 * rr) * 1024 + l0 + x] = t[x][y + 8 * rr];
    __syncthreads();
#pragma unroll
    for (int rr = 0; rr < 4; ++rr)
        t[y + 8 * rr][x] = srcl[(size_t)(l0 + y + 8 * rr) * 64 + e0 + x];
    __syncthreads();
#pragma unroll
    for (int rr = 0; rr < 4; ++rr)
        dstl[(size_t)(e0 + y + 8 * rr) * 1024 + l0 + x] = t[x][y + 8 * rr];
}

// ---------------------------------------------------------------------------
// Flash attention via mma.sync over COMPACTED keys (ntiles per batch).
// ---------------------------------------------------------------------------
#define OQH 0
#define OQL 9216
#define ASTG0 18432
#define ASTG1 36864
#define AMSK_BYTES 110592
#define ATTN_SMEM (110592 + 512)

__device__ __forceinline__ void attn_load_stage(
    const __nv_bfloat16* Kh, const __nv_bfloat16* Kl,
    const __nv_bfloat16* Vth, const __nv_bfloat16* Vtl,
    const float* msrc, uint32_t sb32, int stage, int kt, int tid)
{
    uint32_t base = sb32 + (stage ? ASTG1 : ASTG0) * 2;
#pragma unroll
    for (int rr = 0; rr < 2; ++rr) {
        int u = tid + rr * 256;
        int row = u >> 3, c8 = (u & 7) * 8;
        uint32_t d = base + (row * 72 + c8) * 2;
        const size_t ko = (size_t)(kt * 64 + row) * 64 + c8;
        const size_t vo = (size_t)row * 1024 + kt * 64 + c8;
        cp16(d,             Kh + ko);
        cp16(d + 4608 * 2,  Kl + ko);
        cp16(d + 9216 * 2,  Vth + vo);
        cp16(d + 13824 * 2, Vtl + vo);
    }
    if (tid < 16)
        cp16(sb32 + AMSK_BYTES + stage * 256 + tid * 16, msrc + kt * 64 + tid * 4);
}

__global__ __launch_bounds__(256, 2) void attn_mma_kernel()
{
    extern __shared__ __nv_bfloat16 sb[];
    __nv_bfloat16* sQh = sb + OQH;   // [128][72]
    __nv_bfloat16* sQl = sb + OQL;

    const int tid  = threadIdx.x;
    const int warp = tid >> 5;
    const int lane = tid & 31;
    const int r    = lane >> 2;
    const int cg   = (lane & 3) * 2;
    const int mw   = warp * 16;

    const int q0 = blockIdx.x * 128;
    const int bh = blockIdx.y;
    const int b  = bh >> 3;
    const int hh = bh & 7;

    const int ntiles = (g_nlive[b] + 63) >> 6;

    const __nv_bfloat16* Qh = g_oh + ((size_t)(0 * 64 + bh) * 1024 + q0) * 64;
    const __nv_bfloat16* Ql = g_ol + ((size_t)(0 * 64 + bh) * 1024 + q0) * 64;
    const __nv_bfloat16* Kh = g_oh + ((size_t)(1 * 64 + bh) * 1024) * 64;
    const __nv_bfloat16* Kl = g_ol + ((size_t)(1 * 64 + bh) * 1024) * 64;
    const __nv_bfloat16* Vth = g_vth + (size_t)bh * 64 * 1024;
    const __nv_bfloat16* Vtl = g_vtl + (size_t)bh * 64 * 1024;
    const float* msrc = g_cmask[b];

    const uint32_t sb32 = smem_u32(sb);

    attn_load_stage(Kh, Kl, Vth, Vtl, msrc, sb32, 0, 0, tid);
    CP_COMMIT();

#pragma unroll
    for (int rr = 0; rr < 4; ++rr) {
        int u = tid + rr * 256;
        int row = u >> 3, c8 = (u & 7) * 8;
        *(uint4*)(sQh + row * 72 + c8) = *(const uint4*)(Qh + (size_t)row * 64 + c8);
        *(uint4*)(sQl + row * 72 + c8) = *(const uint4*)(Ql + (size_t)row * 64 + c8);
    }

    float m[2], l[2], o[8][4];
    m[0] = m[1] = -1e30f;
    l[0] = l[1] = 0.f;
#pragma unroll
    for (int n = 0; n < 8; ++n)
#pragma unroll
        for (int j = 0; j < 4; ++j) o[n][j] = 0.f;

    for (int kt = 0; kt < ntiles; ++kt) {
        if (kt + 1 < ntiles) {
            attn_load_stage(Kh, Kl, Vth, Vtl, msrc, sb32, (kt + 1) & 1, kt + 1, tid);
            CP_COMMIT();
            CP_WAIT1();
        } else {
            CP_WAIT0();
        }
        __syncthreads();

        const int cur = kt & 1;
        const __nv_bfloat16* bS = sb + (cur ? ASTG1 : ASTG0);
        const __nv_bfloat16* sKh = bS;
        const __nv_bfloat16* sKl = bS + 4608;
        const __nv_bfloat16* sVh = bS + 9216;
        const __nv_bfloat16* sVl = bS + 13824;
        const float* smask = (const float*)((const char*)sb + AMSK_BYTES + cur * 256);

        // ---- S = Q K^T (split bf16, term-major issue) ----
        float s[8][4];
#pragma unroll
        for (int n = 0; n < 8; ++n)
#pragma unroll
            for (int j = 0; j < 4; ++j) s[n][j] = 0.f;

#pragma unroll
        for (int ks = 0; ks < 4; ++ks) {
            int ro = (mw + r) * 72 + ks * 16 + cg;
            uint32_t qh0 = *(const uint32_t*)(sQh + ro);
            uint32_t qh1 = *(const uint32_t*)(sQh + ro + 8 * 72);
            uint32_t qh2 = *(const uint32_t*)(sQh + ro + 8);
            uint32_t qh3 = *(const uint32_t*)(sQh + ro + 8 * 72 + 8);
            uint32_t ql0 = *(const uint32_t*)(sQl + ro);
            uint32_t ql1 = *(const uint32_t*)(sQl + ro + 8 * 72);
            uint32_t ql2 = *(const uint32_t*)(sQl + ro + 8);
            uint32_t ql3 = *(const uint32_t*)(sQl + ro + 8 * 72 + 8);
#pragma unroll
            for (int hf = 0; hf < 2; ++hf) {
                uint32_t b0[4], b1[4], lb0[4], lb1[4];
#pragma unroll
                for (int j = 0; j < 4; ++j) {
                    int bo = ((hf * 4 + j) * 8 + r) * 72 + ks * 16 + cg;
                    b0[j]  = *(const uint32_t*)(sKh + bo);
                    b1[j]  = *(const uint32_t*)(sKh + bo + 8);
                    lb0[j] = *(const uint32_t*)(sKl + bo);
                    lb1[j] = *(const uint32_t*)(sKl + bo + 8);
                }
#pragma unroll
                for (int j = 0; j < 4; ++j)
                    MMA16816(s[hf*4+j], qh0, qh1, qh2, qh3, b0[j], b1[j]);
#pragma unroll
                for (int j = 0; j < 4; ++j)
                    MMA16816(s[hf*4+j], qh0, qh1, qh2, qh3, lb0[j], lb1[j]);
#pragma unroll
                for (int j = 0; j < 4; ++j)
                    MMA16816(s[hf*4+j], ql0, ql1, ql2, ql3, b0[j], b1[j]);
            }
        }

        // ---- mask (pad slots of last tile) ----
#pragma unroll
        for (int ng = 0; ng < 8; ++ng) {
            float mk0 = smask[ng * 8 + cg];
            float mk1 = smask[ng * 8 + cg + 1];
            if (mk0 == 0.f) { s[ng][0] = -1e30f; s[ng][2] = -1e30f; }
            if (mk1 == 0.f) { s[ng][1] = -1e30f; s[ng][3] = -1e30f; }
        }

        // ---- online softmax on fragments ----
        float rm0 = -1e30f, rm1 = -1e30f;
#pragma unroll
        for (int ng = 0; ng < 8; ++ng) {
            rm0 = fmaxf(rm0, fmaxf(s[ng][0], s[ng][1]));
            rm1 = fmaxf(rm1, fmaxf(s[ng][2], s[ng][3]));
        }
        rm0 = fmaxf(rm0, __shfl_xor_sync(0xffffffffu, rm0, 1));
        rm0 = fmaxf(rm0, __shfl_xor_sync(0xffffffffu, rm0, 2));
        rm1 = fmaxf(rm1, __shfl_xor_sync(0xffffffffu, rm1, 1));
        rm1 = fmaxf(rm1, __shfl_xor_sync(0xffffffffu, rm1, 2));

        float mn0 = fmaxf(m[0], rm0), mn1 = fmaxf(m[1], rm1);
        float sc0 = __expf(m[0] - mn0), sc1 = __expf(m[1] - mn1);
        float rs0 = 0.f, rs1 = 0.f;
#pragma unroll
        for (int ng = 0; ng < 8; ++ng) {
            s[ng][0] = __expf(s[ng][0] - mn0);
            s[ng][1] = __expf(s[ng][1] - mn0);
            s[ng][2] = __expf(s[ng][2] - mn1);
            s[ng][3] = __expf(s[ng][3] - mn1);
            rs0 += s[ng][0] + s[ng][1];
            rs1 += s[ng][2] + s[ng][3];
        }
        rs0 += __shfl_xor_sync(0xffffffffu, rs0, 1);
        rs0 += __shfl_xor_sync(0xffffffffu, rs0, 2);
        rs1 += __shfl_xor_sync(0xffffffffu, rs1, 1);
        rs1 += __shfl_xor_sync(0xffffffffu, rs1, 2);

        l[0] = l[0] * sc0 + rs0;  m[0] = mn0;
        l[1] = l[1] * sc1 + rs1;  m[1] = mn1;
#pragma unroll
        for (int ng = 0; ng < 8; ++ng) {
            o[ng][0] *= sc0; o[ng][1] *= sc0;
            o[ng][2] *= sc1; o[ng][3] *= sc1;
        }

        // ---- O += P V (P from regs, split bf16, term-major issue) ----
#pragma unroll
        for (int ks = 0; ks < 4; ++ks) {
            float* sa = s[2 * ks];
            float* sc = s[2 * ks + 1];
            uint32_t ph0 = packbf(sa[0], sa[1]);
            uint32_t ph1 = packbf(sa[2], sa[3]);
            uint32_t ph2 = packbf(sc[0], sc[1]);
            uint32_t ph3 = packbf(sc[2], sc[3]);
            uint32_t pl0 = packbf(bfres(sa[0]), bfres(sa[1]));
            uint32_t pl1 = packbf(bfres(sa[2]), bfres(sa[3]));
            uint32_t pl2 = packbf(bfres(sc[0]), bfres(sc[1]));
            uint32_t pl3 = packbf(bfres(sc[2]), bfres(sc[3]));
#pragma unroll
            for (int hf = 0; hf < 2; ++hf) {
                uint32_t v0[4], v1[4], w0[4], w1[4];
#pragma unroll
                for (int j = 0; j < 4; ++j) {
                    int bo = ((hf * 4 + j) * 8 + r) * 72 + ks * 16 + cg;
                    v0[j] = *(const uint32_t*)(sVh + bo);
                    v1[j] = *(const uint32_t*)(sVh + bo + 8);
                    w0[j] = *(const uint32_t*)(sVl + bo);
                    w1[j] = *(const uint32_t*)(sVl + bo + 8);
                }
#pragma unroll
                for (int j = 0; j < 4; ++j)
                    MMA16816(o[hf*4+j], ph0, ph1, ph2, ph3, v0[j], v1[j]);
#pragma unroll
                for (int j = 0; j < 4; ++j)
                    MMA16816(o[hf*4+j], ph0, ph1, ph2, ph3, w0[j], w1[j]);
#pragma unroll
                for (int j = 0; j < 4; ++j)
                    MMA16816(o[hf*4+j], pl0, pl1, pl2, pl3, v0[j], v1[j]);
            }
        }
        __syncthreads();
    }

    // epilogue
    float inv0 = 1.f / l[0], inv1 = 1.f / l[1];
    float* row0 = g_conc + ((size_t)b * LQ + q0 + mw + r) * 512 + hh * 64;
    float* row1 = row0 + 8 * 512;
#pragma unroll
    for (int ng = 0; ng < 8; ++ng) {
        *(float2*)(row0 + ng * 8 + cg) = make_float2(o[ng][0] * inv0, o[ng][1] * inv0);
        *(float2*)(row1 + ng * 8 + cg) = make_float2(o[ng][2] * inv1, o[ng][3] * inv1);
    }
}

// ---------------------------------------------------------------------------
// LayerNorm over last dim (512)
// ---------------------------------------------------------------------------
__global__ __launch_bounds__(128) void ln_kernel(
    const float* __restrict__ gamma, const float* __restrict__ beta,
    float* __restrict__ out)
{
    const int row = blockIdx.x;
    const float* x = g_conc + (size_t)row * 512;
    const int tid = threadIdx.x;

    float v[4];
    float s = 0.f;
#pragma unroll
    for (int i = 0; i < 4; ++i) { v[i] = x[tid + i * 128]; s += v[i]; }

    __shared__ float red1[4];
    __shared__ float red2[4];
#pragma unroll
    for (int off = 16; off >= 1; off >>= 1)
        s += __shfl_xor_sync(0xffffffffu, s, off);
    if ((tid & 31) == 0) red1[tid >> 5] = s;
    __syncthreads();
    float mean = (red1[0] + red1[1] + red1[2] + red1[3]) * (1.f / 512.f);

    float q = 0.f;
#pragma unroll
    for (int i = 0; i < 4; ++i) { float d = v[i] - mean; q += d * d; }
#pragma unroll
    for (int off = 16; off >= 1; off >>= 1)
        q += __shfl_xor_sync(0xffffffffu, q, off);
    if ((tid & 31) == 0) red2[tid >> 5] = q;
    __syncthreads();
    float var  = (red2[0] + red2[1] + red2[2] + red2[3]) * (1.f / 512.f);
    float rstd = rsqrtf(var + 1e-14f);
    float g = gamma[0], be = beta[0];
#pragma unroll
    for (int i = 0; i < 4; ++i)
        out[(size_t)row * 512 + tid + i * 128] = (v[i] - mean) * rstd * g + be;
}

// ---------------------------------------------------------------------------
extern "C" void kernel_launch(void* const* d_in, const int* in_sizes, int n_in,
                              void* d_out, int out_size)
{
    const float* query = (const float*)d_in[0];
    const float* key_t = (const float*)d_in[1];
    const float* value = (const float*)d_in[2];
    const float* mask  = (const float*)d_in[3];
    const float* Wq    = (const float*)d_in[4];
    const float* Wk    = (const float*)d_in[5];
    const float* Wv    = (const float*)d_in[6];
    const float* gamma = (const float*)d_in[7];
    const float* beta  = (const float*)d_in[8];
    float* out = (float*)d_out;

    static int attr_set = 0;
    if (!attr_set) {
        cudaFuncSetAttribute(proj_mma_kernel,
                             cudaFuncAttributeMaxDynamicSharedMemorySize, PROJ_SMEM);
        cudaFuncSetAttribute(attn_mma_kernel,
                             cudaFuncAttributeMaxDynamicSharedMemorySize, ATTN_SMEM);
        attr_set = 1;
    }

    index_kernel<<<B, 256>>>(mask);
    convert_x_kernel<<<dim3(4096, 3), 256>>>(query, key_t, value);
    convert_w_kernel<<<dim3(3, 8), 256>>>(Wq, Wk, Wv);

    proj_mma_kernel<<<dim3(LQ / 128, H, 3 * B), 256, PROJ_SMEM>>>();
    vt_kernel<<<dim3(32, 2, 64), dim3(32, 8)>>>();

    attn_mma_kernel<<<dim3(LQ / 128, B * H), 256, ATTN_SMEM>>>();

    ln_kernel<<<B * LQ, 128>>>(gamma, beta, out);
}